// round 5
// baseline (speedup 1.0000x reference)
#include <cuda_runtime.h>
#include <math.h>

#define D_MODEL 1024
#define NHEADS 16
#define HDIM 64
#define BATCH 2
#define SEQ 2048
#define MTOT (BATCH * SEQ)   // 4096 rows

// -------- scratch (allocation-free rule: __device__ globals) --------
__device__ float g_Q[MTOT * D_MODEL];
__device__ float g_K[MTOT * D_MODEL];
__device__ float g_V[MTOT * D_MODEL];

// ============================================================================
// QKV projection GEMM: C[4096,1024] = A[4096,1024] * W[1024,1024] + bias
// BM=128, BN=128, BK=16, 256 threads, 8x8 micro-tile per thread.
// ============================================================================
__global__ __launch_bounds__(256, 2)
void qkv_gemm(const float* __restrict__ A, const float* __restrict__ W,
              const float* __restrict__ bias, float* __restrict__ C) {
    __shared__ float As[128][17];   // +1 pad: breaks bank conflicts on column reads
    __shared__ float Bs[16][128];

    const int tid = threadIdx.x;
    const int tx = tid & 15;        // 0..15 -> N direction
    const int ty = tid >> 4;        // 0..15 -> M direction
    const int m0 = blockIdx.y * 128;
    const int n0 = blockIdx.x * 128;

    float acc[8][8];
#pragma unroll
    for (int i = 0; i < 8; i++)
#pragma unroll
        for (int j = 0; j < 8; j++) acc[i][j] = 0.0f;

    for (int k0 = 0; k0 < D_MODEL; k0 += 16) {
        // Load A tile 128x16 (512 float4, 2 per thread)
#pragma unroll
        for (int i = 0; i < 2; i++) {
            int vid = i * 256 + tid;
            int row = vid >> 2;
            int c4 = (vid & 3) * 4;
            float4 v = *(const float4*)(A + (size_t)(m0 + row) * D_MODEL + k0 + c4);
            As[row][c4 + 0] = v.x; As[row][c4 + 1] = v.y;
            As[row][c4 + 2] = v.z; As[row][c4 + 3] = v.w;
        }
        // Load B tile 16x128 (512 float4, 2 per thread)
#pragma unroll
        for (int i = 0; i < 2; i++) {
            int vid = i * 256 + tid;
            int row = vid >> 5;
            int c4 = (vid & 31) * 4;
            *(float4*)(&Bs[row][c4]) =
                *(const float4*)(W + (size_t)(k0 + row) * D_MODEL + n0 + c4);
        }
        __syncthreads();

#pragma unroll
        for (int kk = 0; kk < 16; kk++) {
            float a[8], b[8];
#pragma unroll
            for (int i = 0; i < 8; i++) a[i] = As[ty * 8 + i][kk];
            float4 b0 = *(float4*)(&Bs[kk][tx * 8]);
            float4 b1 = *(float4*)(&Bs[kk][tx * 8 + 4]);
            b[0] = b0.x; b[1] = b0.y; b[2] = b0.z; b[3] = b0.w;
            b[4] = b1.x; b[5] = b1.y; b[6] = b1.z; b[7] = b1.w;
#pragma unroll
            for (int i = 0; i < 8; i++)
#pragma unroll
                for (int j = 0; j < 8; j++)
                    acc[i][j] += a[i] * b[j];
        }
        __syncthreads();
    }

    // Epilogue: += bias, write C
#pragma unroll
    for (int i = 0; i < 8; i++) {
        int row = m0 + ty * 8 + i;
        float* cp = C + (size_t)row * D_MODEL + n0 + tx * 8;
        const float* bp = bias + n0 + tx * 8;
        float4 o0, o1;
        o0.x = acc[i][0] + bp[0]; o0.y = acc[i][1] + bp[1];
        o0.z = acc[i][2] + bp[2]; o0.w = acc[i][3] + bp[3];
        o1.x = acc[i][4] + bp[4]; o1.y = acc[i][5] + bp[5];
        o1.z = acc[i][6] + bp[6]; o1.w = acc[i][7] + bp[7];
        *(float4*)(cp + 0) = o0;
        *(float4*)(cp + 4) = o1;
    }
}

// ============================================================================
// Flash attention (no scale factor, per reference).
// Grid: (SEQ/BQ, B*H). Block: 256 threads (tx 0..15 = cols, ty 0..15 = rows).
// BQ=128 query rows, BKV=64 key rows per iteration, Hd=64.
// Dynamic smem: Qs[128][65] + Ks[64][65] + Vs[64][65] + Ps[128][65] = 99840 B
// ============================================================================
#define BQ 128
#define BKV 64
#define LDS_PITCH 65
#define ATTN_SMEM_BYTES ((BQ * LDS_PITCH + BKV * LDS_PITCH + BKV * LDS_PITCH + BQ * LDS_PITCH) * 4)

__global__ __launch_bounds__(256)
void attn_kernel(const float* __restrict__ Q, const float* __restrict__ K,
                 const float* __restrict__ V, float* __restrict__ Out) {
    extern __shared__ float sm[];
    float* Qs = sm;                          // BQ  x 65
    float* Ks = Qs + BQ * LDS_PITCH;         // BKV x 65
    float* Vs = Ks + BKV * LDS_PITCH;        // BKV x 65
    float* Ps = Vs + BKV * LDS_PITCH;        // BQ  x 65

    const int tid = threadIdx.x;
    const int tx = tid & 15;      // key-col / out-dim direction (4 each)
    const int ty = tid >> 4;      // query-row direction (8 each)

    const int bh = blockIdx.y;
    const int b = bh / NHEADS;
    const int h = bh % NHEADS;
    const int q0 = blockIdx.x * BQ;

    const float* Qb = Q + (size_t)b * SEQ * D_MODEL + h * HDIM;
    const float* Kb = K + (size_t)b * SEQ * D_MODEL + h * HDIM;
    const float* Vb = V + (size_t)b * SEQ * D_MODEL + h * HDIM;

    // Load Q tile: 128 rows x 64 dims (2048 float4, 8 per thread)
#pragma unroll
    for (int i = 0; i < 8; i++) {
        int vid = i * 256 + tid;
        int row = vid >> 4;          // 16 float4 per row
        int c4 = (vid & 15) * 4;
        float4 v = *(const float4*)(Qb + (size_t)(q0 + row) * D_MODEL + c4);
        float* qp = Qs + row * LDS_PITCH + c4;
        qp[0] = v.x; qp[1] = v.y; qp[2] = v.z; qp[3] = v.w;
    }

    float acc[8][4];
    float mrow[8], lrow[8];
#pragma unroll
    for (int i = 0; i < 8; i++) {
        mrow[i] = -INFINITY;
        lrow[i] = 0.0f;
#pragma unroll
        for (int j = 0; j < 4; j++) acc[i][j] = 0.0f;
    }
    __syncthreads();

    for (int k0 = 0; k0 < SEQ; k0 += BKV) {
        // Load K,V tiles: 64x64 each (1024 float4, 4 per thread each)
#pragma unroll
        for (int i = 0; i < 4; i++) {
            int vid = i * 256 + tid;
            int row = vid >> 4;
            int c4 = (vid & 15) * 4;
            float4 kv = *(const float4*)(Kb + (size_t)(k0 + row) * D_MODEL + c4);
            float* kp = Ks + row * LDS_PITCH + c4;
            kp[0] = kv.x; kp[1] = kv.y; kp[2] = kv.z; kp[3] = kv.w;
            float4 vv = *(const float4*)(Vb + (size_t)(k0 + row) * D_MODEL + c4);
            float* vp = Vs + row * LDS_PITCH + c4;
            vp[0] = vv.x; vp[1] = vv.y; vp[2] = vv.z; vp[3] = vv.w;
        }
        __syncthreads();

        // S = Q * K^T   (rows ty*8+i, cols tx*4+j)
        float s[8][4];
#pragma unroll
        for (int i = 0; i < 8; i++)
#pragma unroll
            for (int j = 0; j < 4; j++) s[i][j] = 0.0f;

#pragma unroll 4
        for (int d = 0; d < HDIM; d++) {
            float qf[8], kf[4];
#pragma unroll
            for (int i = 0; i < 8; i++) qf[i] = Qs[(ty * 8 + i) * LDS_PITCH + d];
#pragma unroll
            for (int j = 0; j < 4; j++) kf[j] = Ks[(tx * 4 + j) * LDS_PITCH + d];
#pragma unroll
            for (int i = 0; i < 8; i++)
#pragma unroll
                for (int j = 0; j < 4; j++)
                    s[i][j] += qf[i] * kf[j];
        }

        // Online softmax per row (16 lanes per row share via shfl)
#pragma unroll
        for (int i = 0; i < 8; i++) {
            float mx = fmaxf(fmaxf(s[i][0], s[i][1]), fmaxf(s[i][2], s[i][3]));
#pragma unroll
            for (int off = 1; off < 16; off <<= 1)
                mx = fmaxf(mx, __shfl_xor_sync(0xffffffffu, mx, off));
            float mnew = fmaxf(mrow[i], mx);
            float p0 = __expf(s[i][0] - mnew);
            float p1 = __expf(s[i][1] - mnew);
            float p2 = __expf(s[i][2] - mnew);
            float p3 = __expf(s[i][3] - mnew);
            float rs = p0 + p1 + p2 + p3;
#pragma unroll
            for (int off = 1; off < 16; off <<= 1)
                rs += __shfl_xor_sync(0xffffffffu, rs, off);
            float scale = __expf(mrow[i] - mnew);
            lrow[i] = lrow[i] * scale + rs;
            mrow[i] = mnew;
#pragma unroll
            for (int j = 0; j < 4; j++) acc[i][j] *= scale;
            float* pp = Ps + (ty * 8 + i) * LDS_PITCH + tx * 4;
            pp[0] = p0; pp[1] = p1; pp[2] = p2; pp[3] = p3;
        }
        __syncthreads();

        // O += P * V   (rows ty*8+i, dims tx*4+j)
#pragma unroll 4
        for (int k = 0; k < BKV; k++) {
            float pf[8], vf[4];
#pragma unroll
            for (int i = 0; i < 8; i++) pf[i] = Ps[(ty * 8 + i) * LDS_PITCH + k];
#pragma unroll
            for (int j = 0; j < 4; j++) vf[j] = Vs[k * LDS_PITCH + tx * 4 + j];
#pragma unroll
            for (int i = 0; i < 8; i++)
#pragma unroll
                for (int j = 0; j < 4; j++)
                    acc[i][j] += pf[i] * vf[j];
        }
        __syncthreads();
    }

    // Epilogue: normalize and write out[b, row, h*64 + dim]
#pragma unroll
    for (int i = 0; i < 8; i++) {
        float inv = 1.0f / lrow[i];
        int row = q0 + ty * 8 + i;
        float4 o;
        o.x = acc[i][0] * inv;
        o.y = acc[i][1] * inv;
        o.z = acc[i][2] * inv;
        o.w = acc[i][3] * inv;
        *(float4*)(Out + ((size_t)b * SEQ + row) * D_MODEL + h * HDIM + tx * 4) = o;
    }
}

// ============================================================================
extern "C" void kernel_launch(void* const* d_in, const int* in_sizes, int n_in,
                              void* d_out, int out_size) {
    (void)in_sizes; (void)n_in; (void)out_size;
    const float* x  = (const float*)d_in[0];
    const float* Wq = (const float*)d_in[1];
    const float* bq = (const float*)d_in[2];
    const float* Wk = (const float*)d_in[3];
    const float* bk = (const float*)d_in[4];
    const float* Wv = (const float*)d_in[5];
    const float* bv = (const float*)d_in[6];
    float* out = (float*)d_out;

    float *qp, *kp, *vp;
    cudaGetSymbolAddress((void**)&qp, g_Q);
    cudaGetSymbolAddress((void**)&kp, g_K);
    cudaGetSymbolAddress((void**)&vp, g_V);

    // Unconditional (idempotent): no static guards allowed in kernel_launch.
    cudaFuncSetAttribute(attn_kernel, cudaFuncAttributeMaxDynamicSharedMemorySize,
                         ATTN_SMEM_BYTES);

    dim3 ggrid(D_MODEL / 128, MTOT / 128);   // (8, 32)
    qkv_gemm<<<ggrid, 256>>>(x, Wq, bq, qp);
    qkv_gemm<<<ggrid, 256>>>(x, Wk, bk, kp);
    qkv_gemm<<<ggrid, 256>>>(x, Wv, bv, vp);

    dim3 agrid(SEQ / BQ, BATCH * NHEADS);    // (16, 32)
    attn_kernel<<<agrid, 256, ATTN_SMEM_BYTES>>>(qp, kp, vp, out);
}

// round 6
// speedup vs baseline: 1.0235x; 1.0235x over previous
#include <cuda_runtime.h>
#include <math.h>

#define D_MODEL 1024
#define NHEADS 16
#define HDIM 64
#define BATCH 2
#define SEQ 2048
#define MTOT (BATCH * SEQ)   // 4096 rows

// -------- scratch (allocation-free rule: __device__ globals) --------
__device__ float g_Q[MTOT * D_MODEL];
__device__ float g_K[MTOT * D_MODEL];
__device__ float g_V[MTOT * D_MODEL];

// ============================================================================
// Fused QKV projection GEMM.
// C[4096,1024] = x[4096,1024] @ W + b for W in {Wq,Wk,Wv} selected by blockIdx.x.
// BM=128, BN=128, BK=16, 256 threads, 8x8 micro-tile, double-buffered smem.
// A tile stored k-major with XOR swizzle so inner-loop reads are LDS.128.
// ============================================================================
__device__ __forceinline__ int a_sw(int kk, int row) {
    // [16][128] k-major, 16B-granule XOR swizzle (conflict-free reads, 2-way stores)
    return kk * 128 + ((((row >> 2) ^ kk) & 31) << 2) + (row & 3);
}

__global__ __launch_bounds__(256, 2)
void qkv_gemm_fused(const float* __restrict__ x,
                    const float* __restrict__ Wq, const float* __restrict__ bq,
                    const float* __restrict__ Wk, const float* __restrict__ bk,
                    const float* __restrict__ Wv, const float* __restrict__ bv,
                    float* __restrict__ Qo, float* __restrict__ Ko,
                    float* __restrict__ Vo) {
    __shared__ float As[2][16 * 128];
    __shared__ float Bs[2][16 * 128];

    const int tid = threadIdx.x;
    const int tx = tid & 15;      // N direction
    const int ty = tid >> 4;      // M direction
    const int nb = blockIdx.x;    // 0..23
    const int mat = nb >> 3;      // 0=Q 1=K 2=V
    const int n0 = (nb & 7) * 128;
    const int m0 = blockIdx.y * 128;

    const float* W    = (mat == 0) ? Wq : (mat == 1 ? Wk : Wv);
    const float* bias = (mat == 0) ? bq : (mat == 1 ? bk : bv);
    float*       C    = (mat == 0) ? Qo : (mat == 1 ? Ko : Vo);

    // per-thread global-load coordinates
    const int ar = tid >> 2;            // A row 0..63 (second: +64)
    const int ac = (tid & 3) * 4;       // A k-col
    const int br = tid >> 5;            // B k-row 0..7 (second: +8)
    const int bc = (tid & 31) * 4;      // B n-col

    const float* Ap = x + (size_t)m0 * D_MODEL;

    float4 a0, a1, b0, b1;
    a0 = *(const float4*)(Ap + (size_t)ar * D_MODEL + ac);
    a1 = *(const float4*)(Ap + (size_t)(ar + 64) * D_MODEL + ac);
    b0 = *(const float4*)(W + (size_t)br * D_MODEL + n0 + bc);
    b1 = *(const float4*)(W + (size_t)(br + 8) * D_MODEL + n0 + bc);
    {
        float* A0 = As[0]; float* B0 = Bs[0];
        A0[a_sw(ac + 0, ar)] = a0.x; A0[a_sw(ac + 1, ar)] = a0.y;
        A0[a_sw(ac + 2, ar)] = a0.z; A0[a_sw(ac + 3, ar)] = a0.w;
        A0[a_sw(ac + 0, ar + 64)] = a1.x; A0[a_sw(ac + 1, ar + 64)] = a1.y;
        A0[a_sw(ac + 2, ar + 64)] = a1.z; A0[a_sw(ac + 3, ar + 64)] = a1.w;
        *(float4*)&B0[br * 128 + bc] = b0;
        *(float4*)&B0[(br + 8) * 128 + bc] = b1;
    }
    __syncthreads();

    float acc[8][8];
#pragma unroll
    for (int i = 0; i < 8; i++)
#pragma unroll
        for (int j = 0; j < 8; j++) acc[i][j] = 0.0f;

    for (int kt = 0; kt < 64; kt++) {
        const float* Ab = As[kt & 1];
        const float* Bb = Bs[kt & 1];
        if (kt < 63) {
            int k0 = (kt + 1) * 16;
            a0 = *(const float4*)(Ap + (size_t)ar * D_MODEL + k0 + ac);
            a1 = *(const float4*)(Ap + (size_t)(ar + 64) * D_MODEL + k0 + ac);
            b0 = *(const float4*)(W + (size_t)(k0 + br) * D_MODEL + n0 + bc);
            b1 = *(const float4*)(W + (size_t)(k0 + br + 8) * D_MODEL + n0 + bc);
        }
#pragma unroll
        for (int kk = 0; kk < 16; kk++) {
            float4 av0 = *(const float4*)&Ab[a_sw(kk, ty * 8)];
            float4 av1 = *(const float4*)&Ab[a_sw(kk, ty * 8 + 4)];
            float4 bv0 = *(const float4*)&Bb[kk * 128 + tx * 4];
            float4 bv1 = *(const float4*)&Bb[kk * 128 + 64 + tx * 4];
            float af[8] = {av0.x, av0.y, av0.z, av0.w, av1.x, av1.y, av1.z, av1.w};
            float bf[8] = {bv0.x, bv0.y, bv0.z, bv0.w, bv1.x, bv1.y, bv1.z, bv1.w};
#pragma unroll
            for (int i = 0; i < 8; i++)
#pragma unroll
                for (int j = 0; j < 8; j++)
                    acc[i][j] += af[i] * bf[j];
        }
        __syncthreads();
        if (kt < 63) {
            float* An = As[(kt + 1) & 1]; float* Bn = Bs[(kt + 1) & 1];
            An[a_sw(ac + 0, ar)] = a0.x; An[a_sw(ac + 1, ar)] = a0.y;
            An[a_sw(ac + 2, ar)] = a0.z; An[a_sw(ac + 3, ar)] = a0.w;
            An[a_sw(ac + 0, ar + 64)] = a1.x; An[a_sw(ac + 1, ar + 64)] = a1.y;
            An[a_sw(ac + 2, ar + 64)] = a1.z; An[a_sw(ac + 3, ar + 64)] = a1.w;
            *(float4*)&Bn[br * 128 + bc] = b0;
            *(float4*)&Bn[(br + 8) * 128 + bc] = b1;
            __syncthreads();
        }
    }

    // Epilogue: cols j<4 -> n0+tx*4+j ; j>=4 -> n0+64+tx*4+(j-4)
#pragma unroll
    for (int i = 0; i < 8; i++) {
        int row = m0 + ty * 8 + i;
        float4 o0, o1;
        o0.x = acc[i][0] + bias[n0 + tx * 4 + 0];
        o0.y = acc[i][1] + bias[n0 + tx * 4 + 1];
        o0.z = acc[i][2] + bias[n0 + tx * 4 + 2];
        o0.w = acc[i][3] + bias[n0 + tx * 4 + 3];
        o1.x = acc[i][4] + bias[n0 + 64 + tx * 4 + 0];
        o1.y = acc[i][5] + bias[n0 + 64 + tx * 4 + 1];
        o1.z = acc[i][6] + bias[n0 + 64 + tx * 4 + 2];
        o1.w = acc[i][7] + bias[n0 + 64 + tx * 4 + 3];
        *(float4*)(C + (size_t)row * D_MODEL + n0 + tx * 4) = o0;
        *(float4*)(C + (size_t)row * D_MODEL + n0 + 64 + tx * 4) = o1;
    }
}

// ============================================================================
// Flash attention, direct-exp (no max subtraction: logit std=8, max ~49 << 88,
// so exp cannot overflow fp32; softmax ratio is identical up to rounding).
// BQ=128, BKV=128, Hd=64. 256 threads: tx=cols(16), ty=rows(16).
// QK^T: 8x8 per thread. P*V: 8x4 per thread.
// Smem: Qs,Ks d-major [64][128] swizzled; Vs [128][68]; Ps k-major [128][128]
// swizzled. All hot-loop reads are conflict-free LDS.128.
// ============================================================================
#define BQ 128
#define BKV 128
#define V_PITCH 68
#define SM_QS 0
#define SM_KS (64 * 128)
#define SM_VS (2 * 64 * 128)
#define SM_PS (2 * 64 * 128 + 128 * V_PITCH)
#define ATTN_SMEM_FLOATS (SM_PS + 128 * 128)
#define ATTN_SMEM_BYTES (ATTN_SMEM_FLOATS * 4)

__device__ __forceinline__ int kq_sw(int d, int col) {
    // [64][128] d-major, 16B-granule XOR swizzle
    return d * 128 + ((((col >> 2) ^ (d >> 2)) & 31) << 2) + (col & 3);
}
__device__ __forceinline__ int p_sw(int col, int row) {
    // [128 cols][128 rows] col-major-of-S, 16B-granule XOR swizzle
    return col * 128 + ((((row >> 2) ^ (col >> 2)) & 31) << 2) + (row & 3);
}

__global__ __launch_bounds__(256)
void attn_kernel(const float* __restrict__ Q, const float* __restrict__ K,
                 const float* __restrict__ V, float* __restrict__ Out) {
    extern __shared__ float sm[];
    float* Qs = sm + SM_QS;
    float* Ks = sm + SM_KS;
    float* Vs = sm + SM_VS;
    float* Ps = sm + SM_PS;

    const int tid = threadIdx.x;
    const int tx = tid & 15;
    const int ty = tid >> 4;

    const int bh = blockIdx.y;
    const int b = bh >> 4;
    const int h = bh & 15;
    const int q0 = blockIdx.x * BQ;

    const float* Qb = Q + (size_t)b * SEQ * D_MODEL + h * HDIM;
    const float* Kb = K + (size_t)b * SEQ * D_MODEL + h * HDIM;
    const float* Vb = V + (size_t)b * SEQ * D_MODEL + h * HDIM;

    // Load Q tile transposed into d-major smem (2048 float4, 8/thread)
#pragma unroll
    for (int i = 0; i < 8; i++) {
        int vid = i * 256 + tid;
        int row = vid >> 4;
        int c4 = (vid & 15) * 4;
        float4 v = *(const float4*)(Qb + (size_t)(q0 + row) * D_MODEL + c4);
        Qs[kq_sw(c4 + 0, row)] = v.x; Qs[kq_sw(c4 + 1, row)] = v.y;
        Qs[kq_sw(c4 + 2, row)] = v.z; Qs[kq_sw(c4 + 3, row)] = v.w;
    }

    float acc[8][4];
    float lrow[8];
#pragma unroll
    for (int i = 0; i < 8; i++) {
        lrow[i] = 0.0f;
#pragma unroll
        for (int j = 0; j < 4; j++) acc[i][j] = 0.0f;
    }
    __syncthreads();

    for (int k0 = 0; k0 < SEQ; k0 += BKV) {
        // Load K (transposed, d-major) and V (k-major) tiles
#pragma unroll
        for (int i = 0; i < 8; i++) {
            int vid = i * 256 + tid;
            int row = vid >> 4;
            int c4 = (vid & 15) * 4;
            float4 kv = *(const float4*)(Kb + (size_t)(k0 + row) * D_MODEL + c4);
            Ks[kq_sw(c4 + 0, row)] = kv.x; Ks[kq_sw(c4 + 1, row)] = kv.y;
            Ks[kq_sw(c4 + 2, row)] = kv.z; Ks[kq_sw(c4 + 3, row)] = kv.w;
            float4 vv = *(const float4*)(Vb + (size_t)(k0 + row) * D_MODEL + c4);
            *(float4*)&Vs[row * V_PITCH + c4] = vv;
        }
        __syncthreads();

        // S = Q K^T : rows ty*8+i, cols j<4 -> tx*4+j, j>=4 -> 64+tx*4+(j-4)
        float s[8][8];
#pragma unroll
        for (int i = 0; i < 8; i++)
#pragma unroll
            for (int j = 0; j < 8; j++) s[i][j] = 0.0f;

#pragma unroll 4
        for (int d = 0; d < HDIM; d++) {
            float4 qa = *(const float4*)&Qs[kq_sw(d, ty * 8)];
            float4 qb = *(const float4*)&Qs[kq_sw(d, ty * 8 + 4)];
            float4 ka = *(const float4*)&Ks[kq_sw(d, tx * 4)];
            float4 kb = *(const float4*)&Ks[kq_sw(d, 64 + tx * 4)];
            float qf[8] = {qa.x, qa.y, qa.z, qa.w, qb.x, qb.y, qb.z, qb.w};
            float kf[8] = {ka.x, ka.y, ka.z, ka.w, kb.x, kb.y, kb.z, kb.w};
#pragma unroll
            for (int i = 0; i < 8; i++)
#pragma unroll
                for (int j = 0; j < 8; j++)
                    s[i][j] += qf[i] * kf[j];
        }

        // exp (no shift), accumulate row sums, store P k-major (vector STS)
#pragma unroll
        for (int jj = 0; jj < 8; jj++) {
            int col = (jj < 4) ? (tx * 4 + jj) : (64 + tx * 4 + (jj - 4));
            float p[8];
#pragma unroll
            for (int i = 0; i < 8; i++) {
                p[i] = __expf(s[i][jj]);
                lrow[i] += p[i];
            }
            float4 v0 = {p[0], p[1], p[2], p[3]};
            float4 v1 = {p[4], p[5], p[6], p[7]};
            *(float4*)&Ps[p_sw(col, ty * 8)] = v0;
            *(float4*)&Ps[p_sw(col, ty * 8 + 4)] = v1;
        }
        __syncthreads();

        // O += P V : rows ty*8+i, dims tx*4+j
#pragma unroll 4
        for (int k = 0; k < BKV; k++) {
            float4 pa = *(const float4*)&Ps[p_sw(k, ty * 8)];
            float4 pb = *(const float4*)&Ps[p_sw(k, ty * 8 + 4)];
            float4 vf = *(const float4*)&Vs[k * V_PITCH + tx * 4];
            float pf[8] = {pa.x, pa.y, pa.z, pa.w, pb.x, pb.y, pb.z, pb.w};
#pragma unroll
            for (int i = 0; i < 8; i++) {
                acc[i][0] += pf[i] * vf.x;
                acc[i][1] += pf[i] * vf.y;
                acc[i][2] += pf[i] * vf.z;
                acc[i][3] += pf[i] * vf.w;
            }
        }
        __syncthreads();
    }

    // Epilogue: reduce row sums across the 16 tx lanes, normalize, write.
#pragma unroll
    for (int i = 0; i < 8; i++) {
        float l = lrow[i];
#pragma unroll
        for (int off = 1; off < 16; off <<= 1)
            l += __shfl_xor_sync(0xffffffffu, l, off);
        float inv = 1.0f / l;
        int row = q0 + ty * 8 + i;
        float4 o;
        o.x = acc[i][0] * inv;
        o.y = acc[i][1] * inv;
        o.z = acc[i][2] * inv;
        o.w = acc[i][3] * inv;
        *(float4*)(Out + ((size_t)b * SEQ + row) * D_MODEL + h * HDIM + tx * 4) = o;
    }
}

// ============================================================================
extern "C" void kernel_launch(void* const* d_in, const int* in_sizes, int n_in,
                              void* d_out, int out_size) {
    (void)in_sizes; (void)n_in; (void)out_size;
    const float* x  = (const float*)d_in[0];
    const float* Wq = (const float*)d_in[1];
    const float* bq = (const float*)d_in[2];
    const float* Wk = (const float*)d_in[3];
    const float* bk = (const float*)d_in[4];
    const float* Wv = (const float*)d_in[5];
    const float* bv = (const float*)d_in[6];
    float* out = (float*)d_out;

    float *qp, *kp, *vp;
    cudaGetSymbolAddress((void**)&qp, g_Q);
    cudaGetSymbolAddress((void**)&kp, g_K);
    cudaGetSymbolAddress((void**)&vp, g_V);

    // Unconditional (idempotent): no static guards allowed in kernel_launch.
    cudaFuncSetAttribute(attn_kernel, cudaFuncAttributeMaxDynamicSharedMemorySize,
                         ATTN_SMEM_BYTES);

    dim3 ggrid(24, MTOT / 128);              // fused Q,K,V: 24 n-blocks x 32 m-blocks
    qkv_gemm_fused<<<ggrid, 256>>>(x, Wq, bq, Wk, bk, Wv, bv, qp, kp, vp);

    dim3 agrid(SEQ / BQ, BATCH * NHEADS);    // (16, 32)
    attn_kernel<<<agrid, 256, ATTN_SMEM_BYTES>>>(qp, kp, vp, out);
}

// round 8
// speedup vs baseline: 2.1089x; 2.0605x over previous
#include <cuda_runtime.h>
#include <cuda_fp16.h>
#include <math.h>
#include <stdint.h>

#define D_MODEL 1024
#define NHEADS 16
#define HDIM 64
#define BATCH 2
#define SEQ 2048
#define MTOT (BATCH * SEQ)   // 4096 rows

// -------- scratch (allocation-free rule: __device__ globals) --------
__device__ __half g_Qhi[MTOT * D_MODEL];
__device__ __half g_Qlo[MTOT * D_MODEL];
__device__ __half g_Khi[MTOT * D_MODEL];
__device__ __half g_Klo[MTOT * D_MODEL];
__device__ __half g_Vhi[MTOT * D_MODEL];

// ============================================================================
// helpers
// ============================================================================
__device__ __forceinline__ uint32_t smem_u32(const void* p) {
    uint32_t a;
    asm("{ .reg .u64 t; cvta.to.shared.u64 t, %1; cvt.u32.u64 %0, t; }"
        : "=r"(a) : "l"(p));
    return a;
}
__device__ __forceinline__ void ldsm4(uint32_t* r, uint32_t addr) {
    asm volatile("ldmatrix.sync.aligned.m8n8.x4.shared.b16 {%0,%1,%2,%3}, [%4];"
                 : "=r"(r[0]), "=r"(r[1]), "=r"(r[2]), "=r"(r[3]) : "r"(addr));
}
__device__ __forceinline__ void ldsm4t(uint32_t* r, uint32_t addr) {
    asm volatile("ldmatrix.sync.aligned.m8n8.x4.trans.shared.b16 {%0,%1,%2,%3}, [%4];"
                 : "=r"(r[0]), "=r"(r[1]), "=r"(r[2]), "=r"(r[3]) : "r"(addr));
}
__device__ __forceinline__ void mma16816(float* d, const uint32_t* a,
                                         uint32_t b0, uint32_t b1) {
    asm volatile(
        "mma.sync.aligned.m16n8k16.row.col.f32.f16.f16.f32 "
        "{%0,%1,%2,%3}, {%4,%5,%6,%7}, {%8,%9}, {%0,%1,%2,%3};"
        : "+f"(d[0]), "+f"(d[1]), "+f"(d[2]), "+f"(d[3])
        : "r"(a[0]), "r"(a[1]), "r"(a[2]), "r"(a[3]), "r"(b0), "r"(b1));
}

// ============================================================================
// Fused QKV projection GEMM (SIMT fp32) -> fp16 hi/lo outputs.
// ============================================================================
__device__ __forceinline__ int a_sw(int kk, int row) {
    return kk * 128 + ((((row >> 2) ^ kk) & 31) << 2) + (row & 3);
}
__device__ __forceinline__ void split_store4h(__half* hi, __half* lo,
                                              float a, float b, float c, float d) {
    __half ha = __float2half_rn(a), hb = __float2half_rn(b);
    __half hc = __float2half_rn(c), hd = __float2half_rn(d);
    __half2 h0; h0.x = ha; h0.y = hb;
    __half2 h1; h1.x = hc; h1.y = hd;
    uint2 hu; hu.x = *reinterpret_cast<uint32_t*>(&h0);
    hu.y = *reinterpret_cast<uint32_t*>(&h1);
    *reinterpret_cast<uint2*>(hi) = hu;
    if (lo) {
        __half la = __float2half_rn(a - __half2float(ha));
        __half lb = __float2half_rn(b - __half2float(hb));
        __half lc = __float2half_rn(c - __half2float(hc));
        __half ld = __float2half_rn(d - __half2float(hd));
        __half2 l0; l0.x = la; l0.y = lb;
        __half2 l1; l1.x = lc; l1.y = ld;
        uint2 lu; lu.x = *reinterpret_cast<uint32_t*>(&l0);
        lu.y = *reinterpret_cast<uint32_t*>(&l1);
        *reinterpret_cast<uint2*>(lo) = lu;
    }
}

__global__ __launch_bounds__(256, 2)
void qkv_gemm_fused(const float* __restrict__ x,
                    const float* __restrict__ Wq, const float* __restrict__ bq,
                    const float* __restrict__ Wk, const float* __restrict__ bk,
                    const float* __restrict__ Wv, const float* __restrict__ bv,
                    __half* __restrict__ qh, __half* __restrict__ ql,
                    __half* __restrict__ kh, __half* __restrict__ kl,
                    __half* __restrict__ vh) {
    __shared__ float As[2][16 * 128];
    __shared__ float Bs[2][16 * 128];

    const int tid = threadIdx.x;
    const int tx = tid & 15;
    const int ty = tid >> 4;
    const int nb = blockIdx.x;
    const int mat = nb >> 3;
    const int n0 = (nb & 7) * 128;
    const int m0 = blockIdx.y * 128;

    const float* W    = (mat == 0) ? Wq : (mat == 1 ? Wk : Wv);
    const float* bias = (mat == 0) ? bq : (mat == 1 ? bk : bv);
    __half* Chi = (mat == 0) ? qh : (mat == 1 ? kh : vh);
    __half* Clo = (mat == 0) ? ql : (mat == 1 ? kl : (__half*)0);

    const int ar = tid >> 2;
    const int ac = (tid & 3) * 4;
    const int br = tid >> 5;
    const int bc = (tid & 31) * 4;

    const float* Ap = x + (size_t)m0 * D_MODEL;

    float4 a0, a1, b0, b1;
    a0 = *(const float4*)(Ap + (size_t)ar * D_MODEL + ac);
    a1 = *(const float4*)(Ap + (size_t)(ar + 64) * D_MODEL + ac);
    b0 = *(const float4*)(W + (size_t)br * D_MODEL + n0 + bc);
    b1 = *(const float4*)(W + (size_t)(br + 8) * D_MODEL + n0 + bc);
    {
        float* A0 = As[0]; float* B0 = Bs[0];
        A0[a_sw(ac + 0, ar)] = a0.x; A0[a_sw(ac + 1, ar)] = a0.y;
        A0[a_sw(ac + 2, ar)] = a0.z; A0[a_sw(ac + 3, ar)] = a0.w;
        A0[a_sw(ac + 0, ar + 64)] = a1.x; A0[a_sw(ac + 1, ar + 64)] = a1.y;
        A0[a_sw(ac + 2, ar + 64)] = a1.z; A0[a_sw(ac + 3, ar + 64)] = a1.w;
        *(float4*)&B0[br * 128 + bc] = b0;
        *(float4*)&B0[(br + 8) * 128 + bc] = b1;
    }
    __syncthreads();

    float acc[8][8];
#pragma unroll
    for (int i = 0; i < 8; i++)
#pragma unroll
        for (int j = 0; j < 8; j++) acc[i][j] = 0.0f;

    for (int kt = 0; kt < 64; kt++) {
        const float* Ab = As[kt & 1];
        const float* Bb = Bs[kt & 1];
        if (kt < 63) {
            int k0 = (kt + 1) * 16;
            a0 = *(const float4*)(Ap + (size_t)ar * D_MODEL + k0 + ac);
            a1 = *(const float4*)(Ap + (size_t)(ar + 64) * D_MODEL + k0 + ac);
            b0 = *(const float4*)(W + (size_t)(k0 + br) * D_MODEL + n0 + bc);
            b1 = *(const float4*)(W + (size_t)(k0 + br + 8) * D_MODEL + n0 + bc);
        }
#pragma unroll
        for (int kk = 0; kk < 16; kk++) {
            float4 av0 = *(const float4*)&Ab[a_sw(kk, ty * 8)];
            float4 av1 = *(const float4*)&Ab[a_sw(kk, ty * 8 + 4)];
            float4 bv0 = *(const float4*)&Bb[kk * 128 + tx * 4];
            float4 bv1 = *(const float4*)&Bb[kk * 128 + 64 + tx * 4];
            float af[8] = {av0.x, av0.y, av0.z, av0.w, av1.x, av1.y, av1.z, av1.w};
            float bf[8] = {bv0.x, bv0.y, bv0.z, bv0.w, bv1.x, bv1.y, bv1.z, bv1.w};
#pragma unroll
            for (int i = 0; i < 8; i++)
#pragma unroll
                for (int j = 0; j < 8; j++)
                    acc[i][j] += af[i] * bf[j];
        }
        __syncthreads();
        if (kt < 63) {
            float* An = As[(kt + 1) & 1]; float* Bn = Bs[(kt + 1) & 1];
            An[a_sw(ac + 0, ar)] = a0.x; An[a_sw(ac + 1, ar)] = a0.y;
            An[a_sw(ac + 2, ar)] = a0.z; An[a_sw(ac + 3, ar)] = a0.w;
            An[a_sw(ac + 0, ar + 64)] = a1.x; An[a_sw(ac + 1, ar + 64)] = a1.y;
            An[a_sw(ac + 2, ar + 64)] = a1.z; An[a_sw(ac + 3, ar + 64)] = a1.w;
            *(float4*)&Bn[br * 128 + bc] = b0;
            *(float4*)&Bn[(br + 8) * 128 + bc] = b1;
            __syncthreads();
        }
    }

#pragma unroll
    for (int i = 0; i < 8; i++) {
        int row = m0 + ty * 8 + i;
        float v0 = acc[i][0] + bias[n0 + tx * 4 + 0];
        float v1 = acc[i][1] + bias[n0 + tx * 4 + 1];
        float v2 = acc[i][2] + bias[n0 + tx * 4 + 2];
        float v3 = acc[i][3] + bias[n0 + tx * 4 + 3];
        float v4 = acc[i][4] + bias[n0 + 64 + tx * 4 + 0];
        float v5 = acc[i][5] + bias[n0 + 64 + tx * 4 + 1];
        float v6 = acc[i][6] + bias[n0 + 64 + tx * 4 + 2];
        float v7 = acc[i][7] + bias[n0 + 64 + tx * 4 + 3];
        size_t o0 = (size_t)row * D_MODEL + n0 + tx * 4;
        size_t o1 = o0 + 64;
        split_store4h(Chi + o0, Clo ? Clo + o0 : (__half*)0, v0, v1, v2, v3);
        split_store4h(Chi + o1, Clo ? Clo + o1 : (__half*)0, v4, v5, v6, v7);
    }
}

// ============================================================================
// HMMA flash attention: fp16 split Q/K (3-pass QK^T), online softmax,
// fp16 P & V (1-pass PV), O in registers. One __syncthreads per KV tile.
// Grid (16, 32), 256 threads (8 warps; warp w owns q-rows w*16..w*16+15).
// ============================================================================
#define SQHI 0
#define SQLO 16384
#define SKHI 32768
#define SKLO 49152
#define SVHI 65536
#define SPS  81920
#define ATTN_SMEM (SPS + 32768)   // 114688 bytes

__global__ __launch_bounds__(256)
void attn_hmma(const __half* __restrict__ Qhi, const __half* __restrict__ Qlo,
               const __half* __restrict__ Khi, const __half* __restrict__ Klo,
               const __half* __restrict__ Vhi, float* __restrict__ Out) {
    extern __shared__ char smc[];
    const uint32_t sb = smem_u32(smc);
    const int tid = threadIdx.x;
    const int w = tid >> 5;
    const int L = tid & 31;
    const int b = blockIdx.y >> 4, h = blockIdx.y & 15;
    const int q0 = blockIdx.x * 128;
    const size_t rowbase = (size_t)b * SEQ;

    const __half* qh_g = Qhi + (rowbase + q0) * D_MODEL + h * HDIM;
    const __half* ql_g = Qlo + (rowbase + q0) * D_MODEL + h * HDIM;

    // ---- load Q hi/lo tiles (swizzled 16B granules) ----
#pragma unroll
    for (int i = 0; i < 4; i++) {
        int vid = i * 256 + tid;
        int r = vid >> 3;
        int g = vid & 7;
        uint32_t off = r * 128 + ((g ^ (r & 7)) << 4);
        *(uint4*)(smc + SQHI + off) = *(const uint4*)(qh_g + (size_t)r * D_MODEL + g * 8);
        *(uint4*)(smc + SQLO + off) = *(const uint4*)(ql_g + (size_t)r * D_MODEL + g * 8);
    }
    __syncthreads();

    // ---- cache Q A-fragments for all 4 k16 steps (hi and lo) ----
    uint32_t qfh[4][4], qfl[4][4];
    {
        int arow = w * 16 + (L & 7) + ((L & 8) ? 8 : 0);
        int acg = (L >> 4) & 1;
#pragma unroll
        for (int ks = 0; ks < 4; ks++) {
            uint32_t off = arow * 128 + ((((ks * 2 + acg) ^ (L & 7)) & 7) << 4);
            ldsm4(qfh[ks], sb + SQHI + off);
            ldsm4(qfl[ks], sb + SQLO + off);
        }
    }

    float S[16][4], O[8][4];
#pragma unroll
    for (int i = 0; i < 8; i++)
#pragma unroll
        for (int j = 0; j < 4; j++) O[i][j] = 0.0f;
    float l0 = 0.0f, l1 = 0.0f, m0 = -INFINITY, m1 = -INFINITY;

    const int brow_off = (L & 7) + ((L & 16) ? 8 : 0);  // QK B-frag n-row offset
    const int bcg = (L >> 3) & 1;                        // QK B-frag k-granule bit

    for (int t = 0; t < 16; t++) {
        __syncthreads();   // prior tile's V/K fully consumed
        const __half* kh_g = Khi + (rowbase + t * 128) * D_MODEL + h * HDIM;
        const __half* kl_g = Klo + (rowbase + t * 128) * D_MODEL + h * HDIM;
        const __half* vh_g = Vhi + (rowbase + t * 128) * D_MODEL + h * HDIM;
#pragma unroll
        for (int i = 0; i < 4; i++) {
            int vid = i * 256 + tid;
            int r = vid >> 3;
            int g = vid & 7;
            uint32_t off = r * 128 + ((g ^ (r & 7)) << 4);
            *(uint4*)(smc + SKHI + off) = *(const uint4*)(kh_g + (size_t)r * D_MODEL + g * 8);
            *(uint4*)(smc + SKLO + off) = *(const uint4*)(kl_g + (size_t)r * D_MODEL + g * 8);
            *(uint4*)(smc + SVHI + off) = *(const uint4*)(vh_g + (size_t)r * D_MODEL + g * 8);
        }
        __syncthreads();

        // ---- S = Q K^T (3-pass split fp16) ----
#pragma unroll
        for (int i = 0; i < 16; i++) {
            S[i][0] = 0.0f; S[i][1] = 0.0f; S[i][2] = 0.0f; S[i][3] = 0.0f;
        }
#pragma unroll
        for (int np = 0; np < 8; np++) {
            int brow = np * 16 + brow_off;
#pragma unroll
            for (int ks = 0; ks < 4; ks++) {
                uint32_t kb[4];
                uint32_t offb = brow * 128 + ((((ks * 2 + bcg) ^ (L & 7)) & 7) << 4);
                ldsm4(kb, sb + SKHI + offb);
                mma16816(S[2 * np],     qfh[ks], kb[0], kb[1]);
                mma16816(S[2 * np + 1], qfh[ks], kb[2], kb[3]);
                mma16816(S[2 * np],     qfl[ks], kb[0], kb[1]);
                mma16816(S[2 * np + 1], qfl[ks], kb[2], kb[3]);
                ldsm4(kb, sb + SKLO + offb);
                mma16816(S[2 * np],     qfh[ks], kb[0], kb[1]);
                mma16816(S[2 * np + 1], qfh[ks], kb[2], kb[3]);
            }
        }

        // ---- online softmax (fully warp-local: warp owns full rows) ----
        float tm0 = -INFINITY, tm1 = -INFINITY;
#pragma unroll
        for (int i = 0; i < 16; i++) {
            tm0 = fmaxf(tm0, fmaxf(S[i][0], S[i][1]));
            tm1 = fmaxf(tm1, fmaxf(S[i][2], S[i][3]));
        }
        tm0 = fmaxf(tm0, __shfl_xor_sync(0xffffffffu, tm0, 1));
        tm0 = fmaxf(tm0, __shfl_xor_sync(0xffffffffu, tm0, 2));
        tm1 = fmaxf(tm1, __shfl_xor_sync(0xffffffffu, tm1, 1));
        tm1 = fmaxf(tm1, __shfl_xor_sync(0xffffffffu, tm1, 2));
        float mn0 = fmaxf(m0, tm0), mn1 = fmaxf(m1, tm1);
        float sc0 = __expf(m0 - mn0), sc1 = __expf(m1 - mn1);
        l0 *= sc0; l1 *= sc1;
        m0 = mn0; m1 = mn1;
#pragma unroll
        for (int i = 0; i < 8; i++) {
            O[i][0] *= sc0; O[i][1] *= sc0;
            O[i][2] *= sc1; O[i][3] *= sc1;
        }
        {
            int prow = w * 16 + (L >> 2);
            int pxr = prow & 7;
            uint32_t pb0 = (uint32_t)(SPS + prow * 256 + 4 * (L & 3));
            uint32_t pb1 = pb0 + 8 * 256;
#pragma unroll
            for (int nt = 0; nt < 16; nt++) {
                float p0 = __expf(S[nt][0] - mn0);
                float p1 = __expf(S[nt][1] - mn0);
                float p2 = __expf(S[nt][2] - mn1);
                float p3 = __expf(S[nt][3] - mn1);
                l0 += p0 + p1;
                l1 += p2 + p3;
                __half2 h01 = __floats2half2_rn(p0, p1);
                __half2 h23 = __floats2half2_rn(p2, p3);
                uint32_t gsh = (uint32_t)(((nt ^ pxr) & 15) << 4);
                *(uint32_t*)(smc + pb0 + gsh) = *reinterpret_cast<uint32_t*>(&h01);
                *(uint32_t*)(smc + pb1 + gsh) = *reinterpret_cast<uint32_t*>(&h23);
            }
        }
        __syncwarp();

        // ---- O += P V (1-pass fp16; P rows are warp-local) ----
        {
            int prow = w * 16 + (L & 7) + ((L & 8) ? 8 : 0);
            int pcg = (L >> 4) & 1;
            int vcg = (L >> 4) & 1;
            int vrow_off = (L & 7) + ((L & 8) ? 8 : 0);
#pragma unroll
            for (int ks = 0; ks < 8; ks++) {
                uint32_t pa[4];
                uint32_t poff = prow * 256 + ((((ks * 2 + pcg) ^ (L & 7)) & 15) << 4);
                ldsm4(pa, sb + SPS + poff);
                int vrow = ks * 16 + vrow_off;
#pragma unroll
                for (int np = 0; np < 4; np++) {
                    uint32_t vb[4];
                    uint32_t voff = vrow * 128 + ((((np * 2 + vcg) ^ (L & 7)) & 7) << 4);
                    ldsm4t(vb, sb + SVHI + voff);
                    mma16816(O[2 * np],     pa, vb[0], vb[1]);
                    mma16816(O[2 * np + 1], pa, vb[2], vb[3]);
                }
            }
        }
    }

    // ---- finalize: reduce l over the quad, normalize, write ----
    l0 += __shfl_xor_sync(0xffffffffu, l0, 1);
    l0 += __shfl_xor_sync(0xffffffffu, l0, 2);
    l1 += __shfl_xor_sync(0xffffffffu, l1, 1);
    l1 += __shfl_xor_sync(0xffffffffu, l1, 2);
    float i0 = 1.0f / l0, i1 = 1.0f / l1;
    int r0 = q0 + w * 16 + (L >> 2);
    float* o0 = Out + (rowbase + r0) * D_MODEL + h * HDIM + 2 * (L & 3);
    float* o1 = o0 + 8 * D_MODEL;
#pragma unroll
    for (int nt = 0; nt < 8; nt++) {
        float2 a; a.x = O[nt][0] * i0; a.y = O[nt][1] * i0;
        float2 c; c.x = O[nt][2] * i1; c.y = O[nt][3] * i1;
        *(float2*)(o0 + nt * 8) = a;
        *(float2*)(o1 + nt * 8) = c;
    }
}

// ============================================================================
extern "C" void kernel_launch(void* const* d_in, const int* in_sizes, int n_in,
                              void* d_out, int out_size) {
    (void)in_sizes; (void)n_in; (void)out_size;
    const float* x  = (const float*)d_in[0];
    const float* Wq = (const float*)d_in[1];
    const float* bq = (const float*)d_in[2];
    const float* Wk = (const float*)d_in[3];
    const float* bk = (const float*)d_in[4];
    const float* Wv = (const float*)d_in[5];
    const float* bv = (const float*)d_in[6];
    float* out = (float*)d_out;

    __half *qh, *ql, *kh, *kl, *vh;
    cudaGetSymbolAddress((void**)&qh, g_Qhi);
    cudaGetSymbolAddress((void**)&ql, g_Qlo);
    cudaGetSymbolAddress((void**)&kh, g_Khi);
    cudaGetSymbolAddress((void**)&kl, g_Klo);
    cudaGetSymbolAddress((void**)&vh, g_Vhi);

    // Unconditional (idempotent): no static guards allowed in kernel_launch.
    cudaFuncSetAttribute(attn_hmma, cudaFuncAttributeMaxDynamicSharedMemorySize,
                         ATTN_SMEM);

    dim3 ggrid(24, MTOT / 128);
    qkv_gemm_fused<<<ggrid, 256>>>(x, Wq, bq, Wk, bk, Wv, bv,
                                   qh, ql, kh, kl, vh);

    dim3 agrid(SEQ / 128, BATCH * NHEADS);
    attn_hmma<<<agrid, 256, ATTN_SMEM>>>(qh, ql, kh, kl, vh, out);
}

// round 9
// speedup vs baseline: 2.9084x; 1.3791x over previous
#include <cuda_runtime.h>
#include <cuda_fp16.h>
#include <math.h>
#include <stdint.h>

#define D_MODEL 1024
#define NHEADS 16
#define HDIM 64
#define BATCH 2
#define SEQ 2048
#define MTOT (BATCH * SEQ)   // 4096 rows

// -------- scratch (allocation-free rule: __device__ globals) --------
__device__ __half g_Xh[MTOT * D_MODEL];
__device__ __half g_Xl[MTOT * D_MODEL];
__device__ __half g_Wh[3 * D_MODEL * D_MODEL];
__device__ __half g_Wl[3 * D_MODEL * D_MODEL];
__device__ __half g_Qhi[MTOT * D_MODEL];
__device__ __half g_Qlo[MTOT * D_MODEL];
__device__ __half g_Khi[MTOT * D_MODEL];
__device__ __half g_Klo[MTOT * D_MODEL];
__device__ __half g_Vhi[MTOT * D_MODEL];

// ============================================================================
// helpers
// ============================================================================
__device__ __forceinline__ uint32_t smem_u32(const void* p) {
    uint32_t a;
    asm("{ .reg .u64 t; cvta.to.shared.u64 t, %1; cvt.u32.u64 %0, t; }"
        : "=r"(a) : "l"(p));
    return a;
}
__device__ __forceinline__ void ldsm4(uint32_t* r, uint32_t addr) {
    asm volatile("ldmatrix.sync.aligned.m8n8.x4.shared.b16 {%0,%1,%2,%3}, [%4];"
                 : "=r"(r[0]), "=r"(r[1]), "=r"(r[2]), "=r"(r[3]) : "r"(addr));
}
__device__ __forceinline__ void ldsm4t(uint32_t* r, uint32_t addr) {
    asm volatile("ldmatrix.sync.aligned.m8n8.x4.trans.shared.b16 {%0,%1,%2,%3}, [%4];"
                 : "=r"(r[0]), "=r"(r[1]), "=r"(r[2]), "=r"(r[3]) : "r"(addr));
}
__device__ __forceinline__ void mma16816(float* d, const uint32_t* a,
                                         uint32_t b0, uint32_t b1) {
    asm volatile(
        "mma.sync.aligned.m16n8k16.row.col.f32.f16.f16.f32 "
        "{%0,%1,%2,%3}, {%4,%5,%6,%7}, {%8,%9}, {%0,%1,%2,%3};"
        : "+f"(d[0]), "+f"(d[1]), "+f"(d[2]), "+f"(d[3])
        : "r"(a[0]), "r"(a[1]), "r"(a[2]), "r"(a[3]), "r"(b0), "r"(b1));
}
__device__ __forceinline__ void cpa16(uint32_t s, const void* g) {
    asm volatile("cp.async.cg.shared.global [%0], [%1], 16;" :: "r"(s), "l"(g));
}
#define CPA_COMMIT() asm volatile("cp.async.commit_group;" ::: "memory")
#define CPA_WAIT1() asm volatile("cp.async.wait_group 1;" ::: "memory")
#define CPA_WAIT0() asm volatile("cp.async.wait_group 0;" ::: "memory")

__device__ __forceinline__ void split_store2h(__half* hi, __half* lo,
                                              float a, float b) {
    __half ha = __float2half_rn(a), hb = __float2half_rn(b);
    __half2 h; h.x = ha; h.y = hb;
    *reinterpret_cast<__half2*>(hi) = h;
    if (lo) {
        __half2 l;
        l.x = __float2half_rn(a - __half2float(ha));
        l.y = __float2half_rn(b - __half2float(hb));
        *reinterpret_cast<__half2*>(lo) = l;
    }
}

// ============================================================================
// Split fp32 -> fp16 hi/lo (vectorized, grid-stride free: exact-size grids)
// ============================================================================
__global__ __launch_bounds__(256)
void split_kernel(const float* __restrict__ src, __half* __restrict__ hi,
                  __half* __restrict__ lo, int n4) {
    int i = blockIdx.x * 256 + threadIdx.x;
    if (i >= n4) return;
    float4 v = reinterpret_cast<const float4*>(src)[i];
    __half ha = __float2half_rn(v.x), hb = __float2half_rn(v.y);
    __half hc = __float2half_rn(v.z), hd = __float2half_rn(v.w);
    __half2 h0; h0.x = ha; h0.y = hb;
    __half2 h1; h1.x = hc; h1.y = hd;
    uint2 hu; hu.x = *reinterpret_cast<uint32_t*>(&h0);
    hu.y = *reinterpret_cast<uint32_t*>(&h1);
    reinterpret_cast<uint2*>(hi)[i] = hu;
    __half2 l0, l1;
    l0.x = __float2half_rn(v.x - __half2float(ha));
    l0.y = __float2half_rn(v.y - __half2float(hb));
    l1.x = __float2half_rn(v.z - __half2float(hc));
    l1.y = __float2half_rn(v.w - __half2float(hd));
    uint2 lu; lu.x = *reinterpret_cast<uint32_t*>(&l0);
    lu.y = *reinterpret_cast<uint32_t*>(&l1);
    reinterpret_cast<uint2*>(lo)[i] = lu;
}

// ============================================================================
// HMMA QKV projection GEMM: C[4096, 3*1024] = x @ {Wq,Wk,Wv} + bias.
// BM=128, BN=128, BK=64, 256 threads, 8 warps (4 m x 2 n), 3-pass fp16 split,
// cp.async double-buffered smem. Epilogue splits q/k to hi/lo fp16, v to hi.
// ============================================================================
#define GOF_AH 0
#define GOF_AL 16384
#define GOF_BH 32768
#define GOF_BL 49152
#define GBUF_BYTES 65536
#define GEMM_SMEM (2 * GBUF_BYTES)   // 131072

__global__ __launch_bounds__(256)
void qkv_hmma(const __half* __restrict__ xh, const __half* __restrict__ xl,
              const __half* __restrict__ Wh_all, const __half* __restrict__ Wl_all,
              const float* __restrict__ bq, const float* __restrict__ bk,
              const float* __restrict__ bv,
              __half* __restrict__ qh, __half* __restrict__ ql,
              __half* __restrict__ kh, __half* __restrict__ kl,
              __half* __restrict__ vh) {
    extern __shared__ char smc[];
    const uint32_t sb = smem_u32(smc);
    const int tid = threadIdx.x;
    const int w = tid >> 5;
    const int L = tid & 31;
    const int nb = blockIdx.x;       // 0..23
    const int mat = nb >> 3;         // 0=Q 1=K 2=V
    const int n0 = (nb & 7) * 128;
    const int m0 = blockIdx.y * 128;
    const int wm = w & 3, wn = w >> 2;

    const __half* Wh = Wh_all + (size_t)mat * D_MODEL * D_MODEL;
    const __half* Wl = Wl_all + (size_t)mat * D_MODEL * D_MODEL;
    const float* bias = (mat == 0) ? bq : (mat == 1 ? bk : bv);
    __half* Chi = (mat == 0) ? qh : (mat == 1 ? kh : vh);
    __half* Clo = (mat == 0) ? ql : (mat == 1 ? kl : (__half*)0);

    // per-thread cp.async coordinates
    const int arr = tid >> 1;               // A row 0..127 (2 granule-pairs)
    const int arg = (tid & 1) * 4;          // A granule base 0 or 4 (x4 granules each)
    const int brr = tid >> 2;               // B k-row 0..63
    const int brg = (tid & 3) * 4;          // B granule base {0,4,8,12}

    auto issue = [&](int buf, int kc) {
        uint32_t base = sb + buf * GBUF_BYTES;
        const __half* ah_g = xh + (size_t)(m0 + arr) * D_MODEL + kc * 64;
        const __half* al_g = xl + (size_t)(m0 + arr) * D_MODEL + kc * 64;
#pragma unroll
        for (int g = 0; g < 4; g++) {
            int gg = arg + g;
            uint32_t off = arr * 128 + (((gg ^ (arr & 7)) & 7) << 4);
            cpa16(base + GOF_AH + off, ah_g + gg * 8);
            cpa16(base + GOF_AL + off, al_g + gg * 8);
        }
        const __half* bh_g = Wh + (size_t)(kc * 64 + brr) * D_MODEL + n0;
        const __half* bl_g = Wl + (size_t)(kc * 64 + brr) * D_MODEL + n0;
#pragma unroll
        for (int g = 0; g < 4; g++) {
            int gg = brg + g;
            uint32_t off = brr * 256 + (((gg ^ (brr & 7)) & 15) << 4);
            cpa16(base + GOF_BH + off, bh_g + gg * 8);
            cpa16(base + GOF_BL + off, bl_g + gg * 8);
        }
    };

    float acc[2][8][4];
#pragma unroll
    for (int i = 0; i < 2; i++)
#pragma unroll
        for (int j = 0; j < 8; j++)
#pragma unroll
            for (int e = 0; e < 4; e++) acc[i][j][e] = 0.0f;

    issue(0, 0);
    CPA_COMMIT();

    const int lrow = L & 15;           // ldsm row-within-16
    const int lcg = (L >> 4) & 1;      // ldsm 16B-granule bit

    for (int kc = 0; kc < 16; kc++) {
        if (kc + 1 < 16) { issue((kc + 1) & 1, kc + 1); CPA_COMMIT(); CPA_WAIT1(); }
        else { CPA_WAIT0(); }
        __syncthreads();

        uint32_t base = sb + (kc & 1) * GBUF_BYTES;
#pragma unroll
        for (int ks = 0; ks < 4; ks++) {
            uint32_t ah[2][4], al[2][4];
#pragma unroll
            for (int mt = 0; mt < 2; mt++) {
                int arow = wm * 32 + mt * 16 + lrow;
                uint32_t off = arow * 128 + ((((ks * 2 + lcg) ^ (arow & 7)) & 7) << 4);
                ldsm4(ah[mt], base + GOF_AH + off);
                ldsm4(al[mt], base + GOF_AL + off);
            }
            int brow = ks * 16 + lrow;
            uint32_t brbase = brow * 256;
            int brx = brow & 7;
#pragma unroll
            for (int nt2 = 0; nt2 < 4; nt2++) {
                int g = wn * 8 + nt2 * 2 + lcg;
                uint32_t off = brbase + (((g ^ brx) & 15) << 4);
                uint32_t bhf[4], blf[4];
                ldsm4t(bhf, base + GOF_BH + off);
                ldsm4t(blf, base + GOF_BL + off);
#pragma unroll
                for (int mt = 0; mt < 2; mt++) {
                    mma16816(acc[mt][nt2 * 2],     ah[mt], bhf[0], bhf[1]);
                    mma16816(acc[mt][nt2 * 2 + 1], ah[mt], bhf[2], bhf[3]);
                    mma16816(acc[mt][nt2 * 2],     al[mt], bhf[0], bhf[1]);
                    mma16816(acc[mt][nt2 * 2 + 1], al[mt], bhf[2], bhf[3]);
                    mma16816(acc[mt][nt2 * 2],     ah[mt], blf[0], blf[1]);
                    mma16816(acc[mt][nt2 * 2 + 1], ah[mt], blf[2], blf[3]);
                }
            }
        }
        __syncthreads();
    }

    // Epilogue: + bias, split-store fp16 hi/lo
#pragma unroll
    for (int mt = 0; mt < 2; mt++) {
        int r = m0 + wm * 32 + mt * 16 + (L >> 2);
#pragma unroll
        for (int nt = 0; nt < 8; nt++) {
            int c = n0 + wn * 64 + nt * 8 + 2 * (L & 3);
            float b0 = bias[c], b1 = bias[c + 1];
            size_t o0 = (size_t)r * D_MODEL + c;
            size_t o1 = o0 + 8 * D_MODEL;
            split_store2h(Chi + o0, Clo ? Clo + o0 : (__half*)0,
                          acc[mt][nt][0] + b0, acc[mt][nt][1] + b1);
            split_store2h(Chi + o1, Clo ? Clo + o1 : (__half*)0,
                          acc[mt][nt][2] + b0, acc[mt][nt][3] + b1);
        }
    }
}

// ============================================================================
// HMMA flash attention (unchanged from round 8): fp16 split Q/K 3-pass QK^T,
// online softmax, fp16 P & V 1-pass PV, O in registers.
// ============================================================================
#define SQHI 0
#define SQLO 16384
#define SKHI 32768
#define SKLO 49152
#define SVHI 65536
#define SPS  81920
#define ATTN_SMEM (SPS + 32768)   // 114688 bytes

__global__ __launch_bounds__(256)
void attn_hmma(const __half* __restrict__ Qhi, const __half* __restrict__ Qlo,
               const __half* __restrict__ Khi, const __half* __restrict__ Klo,
               const __half* __restrict__ Vhi, float* __restrict__ Out) {
    extern __shared__ char smc[];
    const uint32_t sb = smem_u32(smc);
    const int tid = threadIdx.x;
    const int w = tid >> 5;
    const int L = tid & 31;
    const int b = blockIdx.y >> 4, h = blockIdx.y & 15;
    const int q0 = blockIdx.x * 128;
    const size_t rowbase = (size_t)b * SEQ;

    const __half* qh_g = Qhi + (rowbase + q0) * D_MODEL + h * HDIM;
    const __half* ql_g = Qlo + (rowbase + q0) * D_MODEL + h * HDIM;

#pragma unroll
    for (int i = 0; i < 4; i++) {
        int vid = i * 256 + tid;
        int r = vid >> 3;
        int g = vid & 7;
        uint32_t off = r * 128 + ((g ^ (r & 7)) << 4);
        *(uint4*)(smc + SQHI + off) = *(const uint4*)(qh_g + (size_t)r * D_MODEL + g * 8);
        *(uint4*)(smc + SQLO + off) = *(const uint4*)(ql_g + (size_t)r * D_MODEL + g * 8);
    }
    __syncthreads();

    uint32_t qfh[4][4], qfl[4][4];
    {
        int arow = w * 16 + (L & 7) + ((L & 8) ? 8 : 0);
        int acg = (L >> 4) & 1;
#pragma unroll
        for (int ks = 0; ks < 4; ks++) {
            uint32_t off = arow * 128 + ((((ks * 2 + acg) ^ (L & 7)) & 7) << 4);
            ldsm4(qfh[ks], sb + SQHI + off);
            ldsm4(qfl[ks], sb + SQLO + off);
        }
    }

    float S[16][4], O[8][4];
#pragma unroll
    for (int i = 0; i < 8; i++)
#pragma unroll
        for (int j = 0; j < 4; j++) O[i][j] = 0.0f;
    float l0 = 0.0f, l1 = 0.0f, m0 = -INFINITY, m1 = -INFINITY;

    const int brow_off = (L & 7) + ((L & 16) ? 8 : 0);
    const int bcg = (L >> 3) & 1;

    for (int t = 0; t < 16; t++) {
        __syncthreads();
        const __half* kh_g = Khi + (rowbase + t * 128) * D_MODEL + h * HDIM;
        const __half* kl_g = Klo + (rowbase + t * 128) * D_MODEL + h * HDIM;
        const __half* vh_g = Vhi + (rowbase + t * 128) * D_MODEL + h * HDIM;
#pragma unroll
        for (int i = 0; i < 4; i++) {
            int vid = i * 256 + tid;
            int r = vid >> 3;
            int g = vid & 7;
            uint32_t off = r * 128 + ((g ^ (r & 7)) << 4);
            *(uint4*)(smc + SKHI + off) = *(const uint4*)(kh_g + (size_t)r * D_MODEL + g * 8);
            *(uint4*)(smc + SKLO + off) = *(const uint4*)(kl_g + (size_t)r * D_MODEL + g * 8);
            *(uint4*)(smc + SVHI + off) = *(const uint4*)(vh_g + (size_t)r * D_MODEL + g * 8);
        }
        __syncthreads();

#pragma unroll
        for (int i = 0; i < 16; i++) {
            S[i][0] = 0.0f; S[i][1] = 0.0f; S[i][2] = 0.0f; S[i][3] = 0.0f;
        }
#pragma unroll
        for (int np = 0; np < 8; np++) {
            int brow = np * 16 + brow_off;
#pragma unroll
            for (int ks = 0; ks < 4; ks++) {
                uint32_t kb[4];
                uint32_t offb = brow * 128 + ((((ks * 2 + bcg) ^ (L & 7)) & 7) << 4);
                ldsm4(kb, sb + SKHI + offb);
                mma16816(S[2 * np],     qfh[ks], kb[0], kb[1]);
                mma16816(S[2 * np + 1], qfh[ks], kb[2], kb[3]);
                mma16816(S[2 * np],     qfl[ks], kb[0], kb[1]);
                mma16816(S[2 * np + 1], qfl[ks], kb[2], kb[3]);
                ldsm4(kb, sb + SKLO + offb);
                mma16816(S[2 * np],     qfh[ks], kb[0], kb[1]);
                mma16816(S[2 * np + 1], qfh[ks], kb[2], kb[3]);
            }
        }

        float tm0 = -INFINITY, tm1 = -INFINITY;
#pragma unroll
        for (int i = 0; i < 16; i++) {
            tm0 = fmaxf(tm0, fmaxf(S[i][0], S[i][1]));
            tm1 = fmaxf(tm1, fmaxf(S[i][2], S[i][3]));
        }
        tm0 = fmaxf(tm0, __shfl_xor_sync(0xffffffffu, tm0, 1));
        tm0 = fmaxf(tm0, __shfl_xor_sync(0xffffffffu, tm0, 2));
        tm1 = fmaxf(tm1, __shfl_xor_sync(0xffffffffu, tm1, 1));
        tm1 = fmaxf(tm1, __shfl_xor_sync(0xffffffffu, tm1, 2));
        float mn0 = fmaxf(m0, tm0), mn1 = fmaxf(m1, tm1);
        float sc0 = __expf(m0 - mn0), sc1 = __expf(m1 - mn1);
        l0 *= sc0; l1 *= sc1;
        m0 = mn0; m1 = mn1;
#pragma unroll
        for (int i = 0; i < 8; i++) {
            O[i][0] *= sc0; O[i][1] *= sc0;
            O[i][2] *= sc1; O[i][3] *= sc1;
        }
        {
            int prow = w * 16 + (L >> 2);
            int pxr = prow & 7;
            uint32_t pb0 = (uint32_t)(SPS + prow * 256 + 4 * (L & 3));
            uint32_t pb1 = pb0 + 8 * 256;
#pragma unroll
            for (int nt = 0; nt < 16; nt++) {
                float p0 = __expf(S[nt][0] - mn0);
                float p1 = __expf(S[nt][1] - mn0);
                float p2 = __expf(S[nt][2] - mn1);
                float p3 = __expf(S[nt][3] - mn1);
                l0 += p0 + p1;
                l1 += p2 + p3;
                __half2 h01 = __floats2half2_rn(p0, p1);
                __half2 h23 = __floats2half2_rn(p2, p3);
                uint32_t gsh = (uint32_t)(((nt ^ pxr) & 15) << 4);
                *(uint32_t*)(smc + pb0 + gsh) = *reinterpret_cast<uint32_t*>(&h01);
                *(uint32_t*)(smc + pb1 + gsh) = *reinterpret_cast<uint32_t*>(&h23);
            }
        }
        __syncwarp();

        {
            int prow = w * 16 + (L & 7) + ((L & 8) ? 8 : 0);
            int pcg = (L >> 4) & 1;
            int vcg = (L >> 4) & 1;
            int vrow_off = (L & 7) + ((L & 8) ? 8 : 0);
#pragma unroll
            for (int ks = 0; ks < 8; ks++) {
                uint32_t pa[4];
                uint32_t poff = prow * 256 + ((((ks * 2 + pcg) ^ (L & 7)) & 15) << 4);
                ldsm4(pa, sb + SPS + poff);
                int vrow = ks * 16 + vrow_off;
#pragma unroll
                for (int np = 0; np < 4; np++) {
                    uint32_t vb[4];
                    uint32_t voff = vrow * 128 + ((((np * 2 + vcg) ^ (L & 7)) & 7) << 4);
                    ldsm4t(vb, sb + SVHI + voff);
                    mma16816(O[2 * np],     pa, vb[0], vb[1]);
                    mma16816(O[2 * np + 1], pa, vb[2], vb[3]);
                }
            }
        }
    }

    l0 += __shfl_xor_sync(0xffffffffu, l0, 1);
    l0 += __shfl_xor_sync(0xffffffffu, l0, 2);
    l1 += __shfl_xor_sync(0xffffffffu, l1, 1);
    l1 += __shfl_xor_sync(0xffffffffu, l1, 2);
    float i0 = 1.0f / l0, i1 = 1.0f / l1;
    int r0 = q0 + w * 16 + (L >> 2);
    float* o0 = Out + (rowbase + r0) * D_MODEL + h * HDIM + 2 * (L & 3);
    float* o1 = o0 + 8 * D_MODEL;
#pragma unroll
    for (int nt = 0; nt < 8; nt++) {
        float2 a; a.x = O[nt][0] * i0; a.y = O[nt][1] * i0;
        float2 c; c.x = O[nt][2] * i1; c.y = O[nt][3] * i1;
        *(float2*)(o0 + nt * 8) = a;
        *(float2*)(o1 + nt * 8) = c;
    }
}

// ============================================================================
extern "C" void kernel_launch(void* const* d_in, const int* in_sizes, int n_in,
                              void* d_out, int out_size) {
    (void)in_sizes; (void)n_in; (void)out_size;
    const float* x  = (const float*)d_in[0];
    const float* Wq = (const float*)d_in[1];
    const float* bq = (const float*)d_in[2];
    const float* Wk = (const float*)d_in[3];
    const float* bk = (const float*)d_in[4];
    const float* Wv = (const float*)d_in[5];
    const float* bv = (const float*)d_in[6];
    float* out = (float*)d_out;

    __half *xh, *xl, *wh, *wl, *qh, *ql, *kh, *kl, *vh;
    cudaGetSymbolAddress((void**)&xh, g_Xh);
    cudaGetSymbolAddress((void**)&xl, g_Xl);
    cudaGetSymbolAddress((void**)&wh, g_Wh);
    cudaGetSymbolAddress((void**)&wl, g_Wl);
    cudaGetSymbolAddress((void**)&qh, g_Qhi);
    cudaGetSymbolAddress((void**)&ql, g_Qlo);
    cudaGetSymbolAddress((void**)&kh, g_Khi);
    cudaGetSymbolAddress((void**)&kl, g_Klo);
    cudaGetSymbolAddress((void**)&vh, g_Vhi);

    // Unconditional (idempotent): no static guards allowed in kernel_launch.
    cudaFuncSetAttribute(qkv_hmma, cudaFuncAttributeMaxDynamicSharedMemorySize,
                         GEMM_SMEM);
    cudaFuncSetAttribute(attn_hmma, cudaFuncAttributeMaxDynamicSharedMemorySize,
                         ATTN_SMEM);

    // 1) split inputs to fp16 hi/lo
    const int xn4 = MTOT * D_MODEL / 4;       // 1048576
    const int wn4 = D_MODEL * D_MODEL / 4;    // 262144
    split_kernel<<<xn4 / 256, 256>>>(x, xh, xl, xn4);
    split_kernel<<<wn4 / 256, 256>>>(Wq, wh, wl, wn4);
    split_kernel<<<wn4 / 256, 256>>>(Wk, wh + (size_t)D_MODEL * D_MODEL,
                                     wl + (size_t)D_MODEL * D_MODEL, wn4);
    split_kernel<<<wn4 / 256, 256>>>(Wv, wh + 2 * (size_t)D_MODEL * D_MODEL,
                                     wl + 2 * (size_t)D_MODEL * D_MODEL, wn4);

    // 2) HMMA QKV projection
    dim3 ggrid(24, MTOT / 128);
    qkv_hmma<<<ggrid, 256, GEMM_SMEM>>>(xh, xl, wh, wl, bq, bk, bv,
                                        qh, ql, kh, kl, vh);

    // 3) HMMA flash attention
    dim3 agrid(SEQ / 128, BATCH * NHEADS);
    attn_hmma<<<agrid, 256, ATTN_SMEM>>>(qh, ql, kh, kl, vh, out);
}

// round 11
// speedup vs baseline: 3.1541x; 1.0845x over previous
#include <cuda_runtime.h>
#include <cuda_fp16.h>
#include <math.h>
#include <stdint.h>

#define D_MODEL 1024
#define NHEADS 16
#define HDIM 64
#define BATCH 2
#define SEQ 2048
#define MTOT (BATCH * SEQ)   // 4096 rows

// -------- scratch (allocation-free rule: __device__ globals) --------
__device__ __half g_Xh[MTOT * D_MODEL];
__device__ __half g_Xl[MTOT * D_MODEL];
__device__ __half g_Wh[3 * D_MODEL * D_MODEL];
__device__ __half g_Wl[3 * D_MODEL * D_MODEL];
__device__ __half g_Qhi[MTOT * D_MODEL];
__device__ __half g_Qlo[MTOT * D_MODEL];
__device__ __half g_Khi[MTOT * D_MODEL];
__device__ __half g_Klo[MTOT * D_MODEL];
__device__ __half g_Vhi[MTOT * D_MODEL];

// ============================================================================
// helpers
// ============================================================================
__device__ __forceinline__ uint32_t smem_u32(const void* p) {
    uint32_t a;
    asm("{ .reg .u64 t; cvta.to.shared.u64 t, %1; cvt.u32.u64 %0, t; }"
        : "=r"(a) : "l"(p));
    return a;
}
__device__ __forceinline__ void ldsm4(uint32_t* r, uint32_t addr) {
    asm volatile("ldmatrix.sync.aligned.m8n8.x4.shared.b16 {%0,%1,%2,%3}, [%4];"
                 : "=r"(r[0]), "=r"(r[1]), "=r"(r[2]), "=r"(r[3]) : "r"(addr));
}
__device__ __forceinline__ void ldsm4t(uint32_t* r, uint32_t addr) {
    asm volatile("ldmatrix.sync.aligned.m8n8.x4.trans.shared.b16 {%0,%1,%2,%3}, [%4];"
                 : "=r"(r[0]), "=r"(r[1]), "=r"(r[2]), "=r"(r[3]) : "r"(addr));
}
__device__ __forceinline__ void mma16816(float* d, const uint32_t* a,
                                         uint32_t b0, uint32_t b1) {
    asm volatile(
        "mma.sync.aligned.m16n8k16.row.col.f32.f16.f16.f32 "
        "{%0,%1,%2,%3}, {%4,%5,%6,%7}, {%8,%9}, {%0,%1,%2,%3};"
        : "+f"(d[0]), "+f"(d[1]), "+f"(d[2]), "+f"(d[3])
        : "r"(a[0]), "r"(a[1]), "r"(a[2]), "r"(a[3]), "r"(b0), "r"(b1));
}
__device__ __forceinline__ void cpa16(uint32_t s, const void* g) {
    asm volatile("cp.async.cg.shared.global [%0], [%1], 16;" :: "r"(s), "l"(g));
}
#define CPA_COMMIT() asm volatile("cp.async.commit_group;" ::: "memory")
#define CPA_WAIT1() asm volatile("cp.async.wait_group 1;" ::: "memory")
#define CPA_WAIT0() asm volatile("cp.async.wait_group 0;" ::: "memory")

__device__ __forceinline__ void split_store2h(__half* hi, __half* lo,
                                              float a, float b) {
    __half ha = __float2half_rn(a), hb = __float2half_rn(b);
    __half2 h; h.x = ha; h.y = hb;
    *reinterpret_cast<__half2*>(hi) = h;
    if (lo) {
        __half2 l;
        l.x = __float2half_rn(a - __half2float(ha));
        l.y = __float2half_rn(b - __half2float(hb));
        *reinterpret_cast<__half2*>(lo) = l;
    }
}

// ============================================================================
// Split fp32 -> fp16 hi/lo
// ============================================================================
__device__ __forceinline__ void split_body(const float* __restrict__ src,
                                           __half* __restrict__ hi,
                                           __half* __restrict__ lo, int i) {
    float4 v = reinterpret_cast<const float4*>(src)[i];
    __half ha = __float2half_rn(v.x), hb = __float2half_rn(v.y);
    __half hc = __float2half_rn(v.z), hd = __float2half_rn(v.w);
    __half2 h0; h0.x = ha; h0.y = hb;
    __half2 h1; h1.x = hc; h1.y = hd;
    uint2 hu; hu.x = *reinterpret_cast<uint32_t*>(&h0);
    hu.y = *reinterpret_cast<uint32_t*>(&h1);
    reinterpret_cast<uint2*>(hi)[i] = hu;
    __half2 l0, l1;
    l0.x = __float2half_rn(v.x - __half2float(ha));
    l0.y = __float2half_rn(v.y - __half2float(hb));
    l1.x = __float2half_rn(v.z - __half2float(hc));
    l1.y = __float2half_rn(v.w - __half2float(hd));
    uint2 lu; lu.x = *reinterpret_cast<uint32_t*>(&l0);
    lu.y = *reinterpret_cast<uint32_t*>(&l1);
    reinterpret_cast<uint2*>(lo)[i] = lu;
}

__global__ __launch_bounds__(256)
void split_x(const float* __restrict__ src, __half* __restrict__ hi,
             __half* __restrict__ lo) {
    split_body(src, hi, lo, blockIdx.x * 256 + threadIdx.x);
}

__global__ __launch_bounds__(256)
void split_w(const float* __restrict__ wq, const float* __restrict__ wk,
             const float* __restrict__ wv, __half* __restrict__ hi,
             __half* __restrict__ lo) {
    const int mat = blockIdx.y;
    const float* src = (mat == 0) ? wq : (mat == 1 ? wk : wv);
    const size_t off4 = (size_t)mat * (D_MODEL * D_MODEL / 4);
    split_body(src, hi + off4 * 4, lo + off4 * 4, blockIdx.x * 256 + threadIdx.x);
}

// ============================================================================
// HMMA QKV projection GEMM. BM=128, BN=128, BK=64, 8 warps (4m x 2n),
// 3-pass fp16 split, cp.async double buffer, pass-major mma ordering
// (accumulator reuse distance 16 -> no RAW stalls).
// ============================================================================
#define GOF_AH 0
#define GOF_AL 16384
#define GOF_BH 32768
#define GOF_BL 49152
#define GBUF_BYTES 65536
#define GEMM_SMEM (2 * GBUF_BYTES)   // 131072

__global__ __launch_bounds__(256)
void qkv_hmma(const __half* __restrict__ xh, const __half* __restrict__ xl,
              const __half* __restrict__ Wh_all, const __half* __restrict__ Wl_all,
              const float* __restrict__ bq, const float* __restrict__ bk,
              const float* __restrict__ bv,
              __half* __restrict__ qh, __half* __restrict__ ql,
              __half* __restrict__ kh, __half* __restrict__ kl,
              __half* __restrict__ vh) {
    extern __shared__ char smc[];
    const uint32_t sb = smem_u32(smc);
    const int tid = threadIdx.x;
    const int w = tid >> 5;
    const int L = tid & 31;
    const int nb = blockIdx.x;
    const int mat = nb >> 3;
    const int n0 = (nb & 7) * 128;
    const int m0 = blockIdx.y * 128;
    const int wm = w & 3, wn = w >> 2;

    const __half* Wh = Wh_all + (size_t)mat * D_MODEL * D_MODEL;
    const __half* Wl = Wl_all + (size_t)mat * D_MODEL * D_MODEL;
    const float* bias = (mat == 0) ? bq : (mat == 1 ? bk : bv);
    __half* Chi = (mat == 0) ? qh : (mat == 1 ? kh : vh);
    __half* Clo = (mat == 0) ? ql : (mat == 1 ? kl : (__half*)0);

    const int arr = tid >> 1;
    const int arg = (tid & 1) * 4;
    const int brr = tid >> 2;
    const int brg = (tid & 3) * 4;

    auto issue = [&](int buf, int kc) {
        uint32_t base = sb + buf * GBUF_BYTES;
        const __half* ah_g = xh + (size_t)(m0 + arr) * D_MODEL + kc * 64;
        const __half* al_g = xl + (size_t)(m0 + arr) * D_MODEL + kc * 64;
#pragma unroll
        for (int g = 0; g < 4; g++) {
            int gg = arg + g;
            uint32_t off = arr * 128 + (((gg ^ (arr & 7)) & 7) << 4);
            cpa16(base + GOF_AH + off, ah_g + gg * 8);
            cpa16(base + GOF_AL + off, al_g + gg * 8);
        }
        const __half* bh_g = Wh + (size_t)(kc * 64 + brr) * D_MODEL + n0;
        const __half* bl_g = Wl + (size_t)(kc * 64 + brr) * D_MODEL + n0;
#pragma unroll
        for (int g = 0; g < 4; g++) {
            int gg = brg + g;
            uint32_t off = brr * 256 + (((gg ^ (brr & 7)) & 15) << 4);
            cpa16(base + GOF_BH + off, bh_g + gg * 8);
            cpa16(base + GOF_BL + off, bl_g + gg * 8);
        }
    };

    float acc[2][8][4];
#pragma unroll
    for (int i = 0; i < 2; i++)
#pragma unroll
        for (int j = 0; j < 8; j++)
#pragma unroll
            for (int e = 0; e < 4; e++) acc[i][j][e] = 0.0f;

    issue(0, 0);
    CPA_COMMIT();

    const int lrow = L & 15;
    const int lcg = (L >> 4) & 1;

    for (int kc = 0; kc < 16; kc++) {
        if (kc + 1 < 16) { issue((kc + 1) & 1, kc + 1); CPA_COMMIT(); CPA_WAIT1(); }
        else { CPA_WAIT0(); }
        __syncthreads();

        uint32_t base = sb + (kc & 1) * GBUF_BYTES;
#pragma unroll
        for (int ks = 0; ks < 4; ks++) {
            // load ALL fragments for this k16 step first (LSU pipelines them)
            uint32_t ah[2][4], al[2][4];
#pragma unroll
            for (int mt = 0; mt < 2; mt++) {
                int arow = wm * 32 + mt * 16 + lrow;
                uint32_t off = arow * 128 + ((((ks * 2 + lcg) ^ (arow & 7)) & 7) << 4);
                ldsm4(ah[mt], base + GOF_AH + off);
                ldsm4(al[mt], base + GOF_AL + off);
            }
            uint32_t bh[4][4], bl[4][4];
            int brow = ks * 16 + lrow;
            uint32_t brbase = brow * 256;
            int brx = brow & 7;
#pragma unroll
            for (int nt2 = 0; nt2 < 4; nt2++) {
                int g = wn * 8 + nt2 * 2 + lcg;
                uint32_t off = brbase + (((g ^ brx) & 15) << 4);
                ldsm4t(bh[nt2], base + GOF_BH + off);
                ldsm4t(bl[nt2], base + GOF_BL + off);
            }
            // pass-major: 16 independent accumulators per pass
#pragma unroll
            for (int nt2 = 0; nt2 < 4; nt2++)
#pragma unroll
                for (int mt = 0; mt < 2; mt++) {
                    mma16816(acc[mt][nt2 * 2],     ah[mt], bh[nt2][0], bh[nt2][1]);
                    mma16816(acc[mt][nt2 * 2 + 1], ah[mt], bh[nt2][2], bh[nt2][3]);
                }
#pragma unroll
            for (int nt2 = 0; nt2 < 4; nt2++)
#pragma unroll
                for (int mt = 0; mt < 2; mt++) {
                    mma16816(acc[mt][nt2 * 2],     al[mt], bh[nt2][0], bh[nt2][1]);
                    mma16816(acc[mt][nt2 * 2 + 1], al[mt], bh[nt2][2], bh[nt2][3]);
                }
#pragma unroll
            for (int nt2 = 0; nt2 < 4; nt2++)
#pragma unroll
                for (int mt = 0; mt < 2; mt++) {
                    mma16816(acc[mt][nt2 * 2],     ah[mt], bl[nt2][0], bl[nt2][1]);
                    mma16816(acc[mt][nt2 * 2 + 1], ah[mt], bl[nt2][2], bl[nt2][3]);
                }
        }
        __syncthreads();
    }

#pragma unroll
    for (int mt = 0; mt < 2; mt++) {
        int r = m0 + wm * 32 + mt * 16 + (L >> 2);
#pragma unroll
        for (int nt = 0; nt < 8; nt++) {
            int c = n0 + wn * 64 + nt * 8 + 2 * (L & 3);
            float b0 = bias[c], b1 = bias[c + 1];
            size_t o0 = (size_t)r * D_MODEL + c;
            size_t o1 = o0 + 8 * D_MODEL;
            split_store2h(Chi + o0, Clo ? Clo + o0 : (__half*)0,
                          acc[mt][nt][0] + b0, acc[mt][nt][1] + b1);
            split_store2h(Chi + o1, Clo ? Clo + o1 : (__half*)0,
                          acc[mt][nt][2] + b0, acc[mt][nt][3] + b1);
        }
    }
}

// ============================================================================
// HMMA flash attention: cp.async double-buffered K/V, ldsm software pipelining,
// fp16 split Q/K 3-pass QK^T, online softmax, fp16 1-pass PV, O in registers.
// Smem layout (NON-OVERLAPPING — R10's bug was SKV0=49152 aliasing P):
//   [0,16K)   Q hi      [16K,32K) Q lo
//   [32K,64K) P (128 rows x 256 B)
//   [64K,64K+48K) KV buf0 {Khi,Klo,Vhi}   [112K,160K) KV buf1
// ============================================================================
#define SQHI 0
#define SQLO 16384
#define SPS  32768
#define SKV0 65536
#define KVBUF 49152            // KHI +0, KLO +16384, VHI +32768
#define ATTN_SMEM (SKV0 + 2 * KVBUF)   // 163840

__global__ __launch_bounds__(256)
void attn_hmma(const __half* __restrict__ Qhi, const __half* __restrict__ Qlo,
               const __half* __restrict__ Khi, const __half* __restrict__ Klo,
               const __half* __restrict__ Vhi, float* __restrict__ Out) {
    extern __shared__ char smc[];
    const uint32_t sb = smem_u32(smc);
    const int tid = threadIdx.x;
    const int w = tid >> 5;
    const int L = tid & 31;
    const int b = blockIdx.y >> 4, h = blockIdx.y & 15;
    const int q0 = blockIdx.x * 128;
    const size_t rowbase = (size_t)b * SEQ;

    const int ldr_r0 = tid >> 3;       // +32 per i
    const int ldr_g = tid & 7;

    auto kvissue = [&](int buf, int t) {
        uint32_t base = sb + SKV0 + buf * KVBUF;
        const __half* kh_g = Khi + (rowbase + t * 128) * D_MODEL + h * HDIM;
        const __half* kl_g = Klo + (rowbase + t * 128) * D_MODEL + h * HDIM;
        const __half* vh_g = Vhi + (rowbase + t * 128) * D_MODEL + h * HDIM;
#pragma unroll
        for (int i = 0; i < 4; i++) {
            int r = ldr_r0 + i * 32;
            uint32_t off = r * 128 + ((ldr_g ^ (r & 7)) << 4);
            cpa16(base + off,         kh_g + (size_t)r * D_MODEL + ldr_g * 8);
            cpa16(base + 16384 + off, kl_g + (size_t)r * D_MODEL + ldr_g * 8);
            cpa16(base + 32768 + off, vh_g + (size_t)r * D_MODEL + ldr_g * 8);
        }
    };

    // ---- load Q hi/lo (synchronous; one-time) ----
    const __half* qh_g = Qhi + (rowbase + q0) * D_MODEL + h * HDIM;
    const __half* ql_g = Qlo + (rowbase + q0) * D_MODEL + h * HDIM;
#pragma unroll
    for (int i = 0; i < 4; i++) {
        int r = ldr_r0 + i * 32;
        uint32_t off = r * 128 + ((ldr_g ^ (r & 7)) << 4);
        *(uint4*)(smc + SQHI + off) = *(const uint4*)(qh_g + (size_t)r * D_MODEL + ldr_g * 8);
        *(uint4*)(smc + SQLO + off) = *(const uint4*)(ql_g + (size_t)r * D_MODEL + ldr_g * 8);
    }
    kvissue(0, 0);
    CPA_COMMIT();
    __syncthreads();

    // ---- cache Q A-fragments ----
    uint32_t qfh[4][4], qfl[4][4];
    {
        int arow = w * 16 + (L & 7) + ((L & 8) ? 8 : 0);
        int acg = (L >> 4) & 1;
#pragma unroll
        for (int ks = 0; ks < 4; ks++) {
            uint32_t off = arow * 128 + ((((ks * 2 + acg) ^ (L & 7)) & 7) << 4);
            ldsm4(qfh[ks], sb + SQHI + off);
            ldsm4(qfl[ks], sb + SQLO + off);
        }
    }

    float S[16][4], O[8][4];
#pragma unroll
    for (int i = 0; i < 8; i++)
#pragma unroll
        for (int j = 0; j < 4; j++) O[i][j] = 0.0f;
    float l0 = 0.0f, l1 = 0.0f, m0 = -INFINITY, m1 = -INFINITY;

    const int brow_off = (L & 7) + ((L & 16) ? 8 : 0);
    const int bcg = (L >> 3) & 1;
    const int lx7 = L & 7;

    for (int t = 0; t < 16; t++) {
        const int cur = t & 1;
        if (t + 1 < 16) { kvissue(1 - cur, t + 1); CPA_COMMIT(); CPA_WAIT1(); }
        else { CPA_WAIT0(); }
        __syncthreads();

        const uint32_t khb = sb + SKV0 + cur * KVBUF;
        const uint32_t klb = khb + 16384;
        const uint32_t vhb = khb + 32768;

        // ---- S = Q K^T (3-pass, hi-fragment prefetched one step ahead) ----
#pragma unroll
        for (int i = 0; i < 16; i++) {
            S[i][0] = 0.0f; S[i][1] = 0.0f; S[i][2] = 0.0f; S[i][3] = 0.0f;
        }
        uint32_t kbh[4], kbn[4], kbl[4];
        {
            int brow = brow_off;
            ldsm4(kbh, khb + brow * 128 + (((bcg ^ lx7) & 7) << 4));
        }
#pragma unroll
        for (int np = 0; np < 8; np++) {
            int brow = np * 16 + brow_off;
#pragma unroll
            for (int ks = 0; ks < 4; ks++) {
                uint32_t offb = brow * 128 + ((((ks * 2 + bcg) ^ lx7) & 7) << 4);
                ldsm4(kbl, klb + offb);
                mma16816(S[2 * np],     qfh[ks], kbh[0], kbh[1]);
                mma16816(S[2 * np + 1], qfh[ks], kbh[2], kbh[3]);
                if (!(np == 7 && ks == 3)) {   // prefetch next hi fragment
                    int nks = (ks + 1) & 3;
                    int nnp = (ks == 3) ? np + 1 : np;
                    int nbrow = nnp * 16 + brow_off;
                    ldsm4(kbn, khb + nbrow * 128 + ((((nks * 2 + bcg) ^ lx7) & 7) << 4));
                }
                mma16816(S[2 * np],     qfl[ks], kbh[0], kbh[1]);
                mma16816(S[2 * np + 1], qfl[ks], kbh[2], kbh[3]);
                mma16816(S[2 * np],     qfh[ks], kbl[0], kbl[1]);
                mma16816(S[2 * np + 1], qfh[ks], kbl[2], kbl[3]);
                kbh[0] = kbn[0]; kbh[1] = kbn[1]; kbh[2] = kbn[2]; kbh[3] = kbn[3];
            }
        }

        // ---- online softmax (warp-local rows) ----
        float tm0 = -INFINITY, tm1 = -INFINITY;
#pragma unroll
        for (int i = 0; i < 16; i++) {
            tm0 = fmaxf(tm0, fmaxf(S[i][0], S[i][1]));
            tm1 = fmaxf(tm1, fmaxf(S[i][2], S[i][3]));
        }
        tm0 = fmaxf(tm0, __shfl_xor_sync(0xffffffffu, tm0, 1));
        tm0 = fmaxf(tm0, __shfl_xor_sync(0xffffffffu, tm0, 2));
        tm1 = fmaxf(tm1, __shfl_xor_sync(0xffffffffu, tm1, 1));
        tm1 = fmaxf(tm1, __shfl_xor_sync(0xffffffffu, tm1, 2));
        float mn0 = fmaxf(m0, tm0), mn1 = fmaxf(m1, tm1);
        float sc0 = __expf(m0 - mn0), sc1 = __expf(m1 - mn1);
        l0 *= sc0; l1 *= sc1;
        m0 = mn0; m1 = mn1;
#pragma unroll
        for (int i = 0; i < 8; i++) {
            O[i][0] *= sc0; O[i][1] *= sc0;
            O[i][2] *= sc1; O[i][3] *= sc1;
        }
        {
            int prow = w * 16 + (L >> 2);
            int pxr = prow & 7;
            uint32_t pb0 = (uint32_t)(SPS + prow * 256 + 4 * (L & 3));
            uint32_t pb1 = pb0 + 8 * 256;
#pragma unroll
            for (int nt = 0; nt < 16; nt++) {
                float p0 = __expf(S[nt][0] - mn0);
                float p1 = __expf(S[nt][1] - mn0);
                float p2 = __expf(S[nt][2] - mn1);
                float p3 = __expf(S[nt][3] - mn1);
                l0 += p0 + p1;
                l1 += p2 + p3;
                __half2 h01 = __floats2half2_rn(p0, p1);
                __half2 h23 = __floats2half2_rn(p2, p3);
                uint32_t gsh = (uint32_t)(((nt ^ pxr) & 15) << 4);
                *(uint32_t*)(smc + pb0 + gsh) = *reinterpret_cast<uint32_t*>(&h01);
                *(uint32_t*)(smc + pb1 + gsh) = *reinterpret_cast<uint32_t*>(&h23);
            }
        }
        __syncwarp();

        // ---- O += P V (pa/vb fragments prefetched one step ahead) ----
        {
            int prow = w * 16 + (L & 7) + ((L & 8) ? 8 : 0);
            int pcg = (L >> 4) & 1;
            int vrow_off = (L & 7) + ((L & 8) ? 8 : 0);
            uint32_t pa[4], pan[4], vb[4], vbn[4];
            ldsm4(pa, sb + SPS + prow * 256 + (((pcg ^ lx7) & 15) << 4));
            ldsm4t(vb, vhb + vrow_off * 128 + (((pcg ^ lx7) & 7) << 4));
#pragma unroll
            for (int ks = 0; ks < 8; ks++) {
#pragma unroll
                for (int np = 0; np < 4; np++) {
                    if (!(ks == 7 && np == 3)) {   // prefetch next vb
                        int nnp = (np + 1) & 3;
                        int nks = (np == 3) ? ks + 1 : ks;
                        int nvrow = nks * 16 + vrow_off;
                        ldsm4t(vbn, vhb + nvrow * 128 +
                                    ((((nnp * 2 + pcg) ^ lx7) & 7) << 4));
                    }
                    if (np == 0 && ks < 7) {       // prefetch next pa
                        uint32_t poff = prow * 256 +
                            (((((ks + 1) * 2 + pcg) ^ lx7) & 15) << 4);
                        ldsm4(pan, sb + SPS + poff);
                    }
                    mma16816(O[2 * np],     pa, vb[0], vb[1]);
                    mma16816(O[2 * np + 1], pa, vb[2], vb[3]);
                    vb[0] = vbn[0]; vb[1] = vbn[1]; vb[2] = vbn[2]; vb[3] = vbn[3];
                }
                pa[0] = pan[0]; pa[1] = pan[1]; pa[2] = pan[2]; pa[3] = pan[3];
            }
        }
        __syncthreads();   // buf[cur] fully consumed before next prefetch overwrites
    }

    // ---- finalize ----
    l0 += __shfl_xor_sync(0xffffffffu, l0, 1);
    l0 += __shfl_xor_sync(0xffffffffu, l0, 2);
    l1 += __shfl_xor_sync(0xffffffffu, l1, 1);
    l1 += __shfl_xor_sync(0xffffffffu, l1, 2);
    float i0 = 1.0f / l0, i1 = 1.0f / l1;
    int r0 = q0 + w * 16 + (L >> 2);
    float* o0 = Out + (rowbase + r0) * D_MODEL + h * HDIM + 2 * (L & 3);
    float* o1 = o0 + 8 * D_MODEL;
#pragma unroll
    for (int nt = 0; nt < 8; nt++) {
        float2 a; a.x = O[nt][0] * i0; a.y = O[nt][1] * i0;
        float2 c; c.x = O[nt][2] * i1; c.y = O[nt][3] * i1;
        *(float2*)(o0 + nt * 8) = a;
        *(float2*)(o1 + nt * 8) = c;
    }
}

// ============================================================================
extern "C" void kernel_launch(void* const* d_in, const int* in_sizes, int n_in,
                              void* d_out, int out_size) {
    (void)in_sizes; (void)n_in; (void)out_size;
    const float* x  = (const float*)d_in[0];
    const float* Wq = (const float*)d_in[1];
    const float* bq = (const float*)d_in[2];
    const float* Wk = (const float*)d_in[3];
    const float* bk = (const float*)d_in[4];
    const float* Wv = (const float*)d_in[5];
    const float* bv = (const float*)d_in[6];
    float* out = (float*)d_out;

    __half *xh, *xl, *wh, *wl, *qh, *ql, *kh, *kl, *vh;
    cudaGetSymbolAddress((void**)&xh, g_Xh);
    cudaGetSymbolAddress((void**)&xl, g_Xl);
    cudaGetSymbolAddress((void**)&wh, g_Wh);
    cudaGetSymbolAddress((void**)&wl, g_Wl);
    cudaGetSymbolAddress((void**)&qh, g_Qhi);
    cudaGetSymbolAddress((void**)&ql, g_Qlo);
    cudaGetSymbolAddress((void**)&kh, g_Khi);
    cudaGetSymbolAddress((void**)&kl, g_Klo);
    cudaGetSymbolAddress((void**)&vh, g_Vhi);

    // Unconditional (idempotent): no static guards allowed in kernel_launch.
    cudaFuncSetAttribute(qkv_hmma, cudaFuncAttributeMaxDynamicSharedMemorySize,
                         GEMM_SMEM);
    cudaFuncSetAttribute(attn_hmma, cudaFuncAttributeMaxDynamicSharedMemorySize,
                         ATTN_SMEM);

    // 1) split inputs to fp16 hi/lo
    const int xn4 = MTOT * D_MODEL / 4;       // 1048576
    const int wn4 = D_MODEL * D_MODEL / 4;    // 262144
    split_x<<<xn4 / 256, 256>>>(x, xh, xl);
    dim3 wgrid(wn4 / 256, 3);
    split_w<<<wgrid, 256>>>(Wq, Wk, Wv, wh, wl);

    // 2) HMMA QKV projection
    dim3 ggrid(24, MTOT / 128);
    qkv_hmma<<<ggrid, 256, GEMM_SMEM>>>(xh, xl, wh, wl, bq, bk, bv,
                                        qh, ql, kh, kl, vh);

    // 3) HMMA flash attention
    dim3 agrid(SEQ / 128, BATCH * NHEADS);
    attn_hmma<<<agrid, 256, ATTN_SMEM>>>(qh, ql, kh, kl, vh, out);
}

// round 13
// speedup vs baseline: 3.6793x; 1.1665x over previous
#include <cuda_runtime.h>
#include <cuda_fp16.h>
#include <math.h>
#include <stdint.h>

#define D_MODEL 1024
#define NHEADS 16
#define HDIM 64
#define BATCH 2
#define SEQ 2048
#define MTOT (BATCH * SEQ)   // 4096 rows

// -------- scratch (allocation-free rule: __device__ globals) --------
__device__ __half g_Xh[MTOT * D_MODEL];
__device__ __half g_Xl[MTOT * D_MODEL];
__device__ __half g_Wh[3 * D_MODEL * D_MODEL];
__device__ __half g_Wl[3 * D_MODEL * D_MODEL];
__device__ __half g_Qhi[MTOT * D_MODEL];
__device__ __half g_Qlo[MTOT * D_MODEL];
__device__ __half g_Khi[MTOT * D_MODEL];
__device__ __half g_Klo[MTOT * D_MODEL];
__device__ __half g_Vhi[MTOT * D_MODEL];

// ============================================================================
// helpers
// ============================================================================
__device__ __forceinline__ uint32_t smem_u32(const void* p) {
    uint32_t a;
    asm("{ .reg .u64 t; cvta.to.shared.u64 t, %1; cvt.u32.u64 %0, t; }"
        : "=r"(a) : "l"(p));
    return a;
}
__device__ __forceinline__ void ldsm4(uint32_t* r, uint32_t addr) {
    asm volatile("ldmatrix.sync.aligned.m8n8.x4.shared.b16 {%0,%1,%2,%3}, [%4];"
                 : "=r"(r[0]), "=r"(r[1]), "=r"(r[2]), "=r"(r[3]) : "r"(addr));
}
__device__ __forceinline__ void ldsm4t(uint32_t* r, uint32_t addr) {
    asm volatile("ldmatrix.sync.aligned.m8n8.x4.trans.shared.b16 {%0,%1,%2,%3}, [%4];"
                 : "=r"(r[0]), "=r"(r[1]), "=r"(r[2]), "=r"(r[3]) : "r"(addr));
}
__device__ __forceinline__ void mma16816(float* d, const uint32_t* a,
                                         uint32_t b0, uint32_t b1) {
    asm volatile(
        "mma.sync.aligned.m16n8k16.row.col.f32.f16.f16.f32 "
        "{%0,%1,%2,%3}, {%4,%5,%6,%7}, {%8,%9}, {%0,%1,%2,%3};"
        : "+f"(d[0]), "+f"(d[1]), "+f"(d[2]), "+f"(d[3])
        : "r"(a[0]), "r"(a[1]), "r"(a[2]), "r"(a[3]), "r"(b0), "r"(b1));
}
__device__ __forceinline__ void cpa16(uint32_t s, const void* g) {
    asm volatile("cp.async.cg.shared.global [%0], [%1], 16;" :: "r"(s), "l"(g));
}
#define CPA_COMMIT() asm volatile("cp.async.commit_group;" ::: "memory")
#define CPA_WAIT1() asm volatile("cp.async.wait_group 1;" ::: "memory")
#define CPA_WAIT0() asm volatile("cp.async.wait_group 0;" ::: "memory")

__device__ __forceinline__ void split_store2h(__half* hi, __half* lo,
                                              float a, float b) {
    __half ha = __float2half_rn(a), hb = __float2half_rn(b);
    __half2 h; h.x = ha; h.y = hb;
    *reinterpret_cast<__half2*>(hi) = h;
    if (lo) {
        __half2 l;
        l.x = __float2half_rn(a - __half2float(ha));
        l.y = __float2half_rn(b - __half2float(hb));
        *reinterpret_cast<__half2*>(lo) = l;
    }
}

// ============================================================================
// Split fp32 -> fp16 hi/lo
// ============================================================================
__device__ __forceinline__ void split_body(const float* __restrict__ src,
                                           __half* __restrict__ hi,
                                           __half* __restrict__ lo, int i) {
    float4 v = reinterpret_cast<const float4*>(src)[i];
    __half ha = __float2half_rn(v.x), hb = __float2half_rn(v.y);
    __half hc = __float2half_rn(v.z), hd = __float2half_rn(v.w);
    __half2 h0; h0.x = ha; h0.y = hb;
    __half2 h1; h1.x = hc; h1.y = hd;
    uint2 hu; hu.x = *reinterpret_cast<uint32_t*>(&h0);
    hu.y = *reinterpret_cast<uint32_t*>(&h1);
    reinterpret_cast<uint2*>(hi)[i] = hu;
    __half2 l0, l1;
    l0.x = __float2half_rn(v.x - __half2float(ha));
    l0.y = __float2half_rn(v.y - __half2float(hb));
    l1.x = __float2half_rn(v.z - __half2float(hc));
    l1.y = __float2half_rn(v.w - __half2float(hd));
    uint2 lu; lu.x = *reinterpret_cast<uint32_t*>(&l0);
    lu.y = *reinterpret_cast<uint32_t*>(&l1);
    reinterpret_cast<uint2*>(lo)[i] = lu;
}

__global__ __launch_bounds__(256)
void split_x(const float* __restrict__ src, __half* __restrict__ hi,
             __half* __restrict__ lo) {
    split_body(src, hi, lo, blockIdx.x * 256 + threadIdx.x);
}

__global__ __launch_bounds__(256)
void split_w(const float* __restrict__ wq, const float* __restrict__ wk,
             const float* __restrict__ wv, __half* __restrict__ hi,
             __half* __restrict__ lo) {
    const int mat = blockIdx.y;
    const float* src = (mat == 0) ? wq : (mat == 1 ? wk : wv);
    const size_t off4 = (size_t)mat * (D_MODEL * D_MODEL / 4);
    split_body(src, hi + off4 * 4, lo + off4 * 4, blockIdx.x * 256 + threadIdx.x);
}

// ============================================================================
// HMMA QKV projection GEMM. BM=128, BN=128, BK=32, 8 warps (4m x 2n),
// 3-pass fp16 split, cp.async double buffer. 64KB smem + <=128 regs
// -> 2 CTAs/SM (4 warps/SMSP hides RAW/LDSM latency).
// A tile: 128r x 32c (64B rows, granule swizzle g^((r>>1)&3)).
// B tile: 32r x 128c (256B rows, granule swizzle g^(r&7)).
// ============================================================================
#define GOF_AH 0
#define GOF_AL 8192
#define GOF_BH 16384
#define GOF_BL 24576
#define GBUF_BYTES 32768
#define GEMM_SMEM (2 * GBUF_BYTES)   // 65536

__global__ __launch_bounds__(256, 2)
void qkv_hmma(const __half* __restrict__ xh, const __half* __restrict__ xl,
              const __half* __restrict__ Wh_all, const __half* __restrict__ Wl_all,
              const float* __restrict__ bq, const float* __restrict__ bk,
              const float* __restrict__ bv,
              __half* __restrict__ qh, __half* __restrict__ ql,
              __half* __restrict__ kh, __half* __restrict__ kl,
              __half* __restrict__ vh) {
    extern __shared__ char smc[];
    const uint32_t sb = smem_u32(smc);
    const int tid = threadIdx.x;
    const int w = tid >> 5;
    const int L = tid & 31;
    const int nb = blockIdx.x;
    const int mat = nb >> 3;
    const int n0 = (nb & 7) * 128;
    const int m0 = blockIdx.y * 128;
    const int wm = w & 3, wn = w >> 2;

    const __half* Wh = Wh_all + (size_t)mat * D_MODEL * D_MODEL;
    const __half* Wl = Wl_all + (size_t)mat * D_MODEL * D_MODEL;
    const float* bias = (mat == 0) ? bq : (mat == 1 ? bk : bv);
    __half* Chi = (mat == 0) ? qh : (mat == 1 ? kh : vh);
    __half* Clo = (mat == 0) ? ql : (mat == 1 ? kl : (__half*)0);

    // cp.async coords: A 128 rows x 4 granules (2/thread); B 32 rows x 16 (2/thread)
    const int ar = tid >> 1;
    const int ag0 = (tid & 1) * 2;
    const int br = tid >> 3;
    const int bg0 = (tid & 7) * 2;

    auto issue = [&](int buf, int kc) {
        uint32_t base = sb + buf * GBUF_BYTES;
        const __half* ah_g = xh + (size_t)(m0 + ar) * D_MODEL + kc * 32;
        const __half* al_g = xl + (size_t)(m0 + ar) * D_MODEL + kc * 32;
#pragma unroll
        for (int gi = 0; gi < 2; gi++) {
            int g = ag0 + gi;
            uint32_t off = ar * 64 + (((g ^ ((ar >> 1) & 3)) & 3) << 4);
            cpa16(base + GOF_AH + off, ah_g + g * 8);
            cpa16(base + GOF_AL + off, al_g + g * 8);
        }
        const __half* bh_g = Wh + (size_t)(kc * 32 + br) * D_MODEL + n0;
        const __half* bl_g = Wl + (size_t)(kc * 32 + br) * D_MODEL + n0;
#pragma unroll
        for (int gi = 0; gi < 2; gi++) {
            int g = bg0 + gi;
            uint32_t off = br * 256 + (((g ^ (br & 7)) & 15) << 4);
            cpa16(base + GOF_BH + off, bh_g + g * 8);
            cpa16(base + GOF_BL + off, bl_g + g * 8);
        }
    };

    float acc[2][8][4];
#pragma unroll
    for (int i = 0; i < 2; i++)
#pragma unroll
        for (int j = 0; j < 8; j++)
#pragma unroll
            for (int e = 0; e < 4; e++) acc[i][j][e] = 0.0f;

    issue(0, 0);
    CPA_COMMIT();

    const int lrow = L & 15;
    const int lcg = (L >> 4) & 1;

    for (int kc = 0; kc < 32; kc++) {
        if (kc + 1 < 32) { issue((kc + 1) & 1, kc + 1); CPA_COMMIT(); CPA_WAIT1(); }
        else { CPA_WAIT0(); }
        __syncthreads();

        uint32_t base = sb + (kc & 1) * GBUF_BYTES;
#pragma unroll
        for (int ks = 0; ks < 2; ks++) {
            uint32_t ah[2][4], al[2][4];
#pragma unroll
            for (int mt = 0; mt < 2; mt++) {
                int arow = wm * 32 + mt * 16 + lrow;
                int ga = ks * 2 + lcg;
                uint32_t off = arow * 64 + (((ga ^ ((arow >> 1) & 3)) & 3) << 4);
                ldsm4(ah[mt], base + GOF_AH + off);
                ldsm4(al[mt], base + GOF_AL + off);
            }
            int brow = ks * 16 + lrow;
            uint32_t brbase = brow * 256;
            int brx = brow & 7;
            // process b in halves (nt2 pairs) to cap registers
#pragma unroll
            for (int hf = 0; hf < 2; hf++) {
                uint32_t bh[2][4], bl[2][4];
#pragma unroll
                for (int j = 0; j < 2; j++) {
                    int nt2 = hf * 2 + j;
                    int g = wn * 8 + nt2 * 2 + lcg;
                    uint32_t off = brbase + (((g ^ brx) & 15) << 4);
                    ldsm4t(bh[j], base + GOF_BH + off);
                    ldsm4t(bl[j], base + GOF_BL + off);
                }
                // pass-major over this half: acc reuse distance 8
#pragma unroll
                for (int j = 0; j < 2; j++)
#pragma unroll
                    for (int mt = 0; mt < 2; mt++) {
                        int nt2 = hf * 2 + j;
                        mma16816(acc[mt][nt2 * 2],     ah[mt], bh[j][0], bh[j][1]);
                        mma16816(acc[mt][nt2 * 2 + 1], ah[mt], bh[j][2], bh[j][3]);
                    }
#pragma unroll
                for (int j = 0; j < 2; j++)
#pragma unroll
                    for (int mt = 0; mt < 2; mt++) {
                        int nt2 = hf * 2 + j;
                        mma16816(acc[mt][nt2 * 2],     al[mt], bh[j][0], bh[j][1]);
                        mma16816(acc[mt][nt2 * 2 + 1], al[mt], bh[j][2], bh[j][3]);
                    }
#pragma unroll
                for (int j = 0; j < 2; j++)
#pragma unroll
                    for (int mt = 0; mt < 2; mt++) {
                        int nt2 = hf * 2 + j;
                        mma16816(acc[mt][nt2 * 2],     ah[mt], bl[j][0], bl[j][1]);
                        mma16816(acc[mt][nt2 * 2 + 1], ah[mt], bl[j][2], bl[j][3]);
                    }
            }
        }
        __syncthreads();
    }

#pragma unroll
    for (int mt = 0; mt < 2; mt++) {
        int r = m0 + wm * 32 + mt * 16 + (L >> 2);
#pragma unroll
        for (int nt = 0; nt < 8; nt++) {
            int c = n0 + wn * 64 + nt * 8 + 2 * (L & 3);
            float b0 = bias[c], b1 = bias[c + 1];
            size_t o0 = (size_t)r * D_MODEL + c;
            size_t o1 = o0 + 8 * D_MODEL;
            split_store2h(Chi + o0, Clo ? Clo + o0 : (__half*)0,
                          acc[mt][nt][0] + b0, acc[mt][nt][1] + b1);
            split_store2h(Chi + o1, Clo ? Clo + o1 : (__half*)0,
                          acc[mt][nt][2] + b0, acc[mt][nt][3] + b1);
        }
    }
}

// ============================================================================
// HMMA flash attention, BKV=64: cp.async double-buffered K/V, fp16 split Q/K
// 3-pass QK^T, online softmax, fp16 1-pass PV, O in registers.
// 96KB smem + ~110 regs -> 2 CTAs/SM. No manual prefetch (occupancy hides).
// Layout: [0,16K) Qhi  [16K,32K) Qlo  [32K,48K) P (128r x 128B)
//         [48K,72K) KV buf0 {Khi 8K, Klo 8K, Vhi 8K}  [72K,96K) KV buf1
// ============================================================================
#define SQHI 0
#define SQLO 16384
#define SPS  32768
#define SKV0 49152
#define KVBUF 24576
#define ATTN_SMEM (SKV0 + 2 * KVBUF)   // 98304

__global__ __launch_bounds__(256, 2)
void attn_hmma(const __half* __restrict__ Qhi, const __half* __restrict__ Qlo,
               const __half* __restrict__ Khi, const __half* __restrict__ Klo,
               const __half* __restrict__ Vhi, float* __restrict__ Out) {
    extern __shared__ char smc[];
    const uint32_t sb = smem_u32(smc);
    const int tid = threadIdx.x;
    const int w = tid >> 5;
    const int L = tid & 31;
    const int b = blockIdx.y >> 4, h = blockIdx.y & 15;
    const int q0 = blockIdx.x * 128;
    const size_t rowbase = (size_t)b * SEQ;

    // KV cp.async coords: 64 rows x 8 granules per layer, 2 granules/thread
    const int kvr = tid >> 2;
    const int kvg0 = (tid & 3) * 2;

    auto kvissue = [&](int buf, int t) {
        uint32_t base = sb + SKV0 + buf * KVBUF;
        const __half* kh_g = Khi + (rowbase + t * 64 + kvr) * D_MODEL + h * HDIM;
        const __half* kl_g = Klo + (rowbase + t * 64 + kvr) * D_MODEL + h * HDIM;
        const __half* vh_g = Vhi + (rowbase + t * 64 + kvr) * D_MODEL + h * HDIM;
#pragma unroll
        for (int gi = 0; gi < 2; gi++) {
            int g = kvg0 + gi;
            uint32_t off = kvr * 128 + (((g ^ (kvr & 7)) & 7) << 4);
            cpa16(base + off,         kh_g + g * 8);
            cpa16(base + 8192 + off,  kl_g + g * 8);
            cpa16(base + 16384 + off, vh_g + g * 8);
        }
    };

    // ---- load Q hi/lo (synchronous; one-time) ----
    const __half* qh_g = Qhi + (rowbase + q0) * D_MODEL + h * HDIM;
    const __half* ql_g = Qlo + (rowbase + q0) * D_MODEL + h * HDIM;
#pragma unroll
    for (int i = 0; i < 4; i++) {
        int vid = i * 256 + tid;
        int r = vid >> 3;
        int g = vid & 7;
        uint32_t off = r * 128 + ((g ^ (r & 7)) << 4);
        *(uint4*)(smc + SQHI + off) = *(const uint4*)(qh_g + (size_t)r * D_MODEL + g * 8);
        *(uint4*)(smc + SQLO + off) = *(const uint4*)(ql_g + (size_t)r * D_MODEL + g * 8);
    }
    kvissue(0, 0);
    CPA_COMMIT();
    __syncthreads();

    float S[8][4], O[8][4];
#pragma unroll
    for (int i = 0; i < 8; i++)
#pragma unroll
        for (int j = 0; j < 4; j++) O[i][j] = 0.0f;
    float l0 = 0.0f, l1 = 0.0f, m0 = -INFINITY, m1 = -INFINITY;

    const int arow = w * 16 + (L & 15);            // Q/P A-operand row
    const int acg = (L >> 4) & 1;
    const int brow_off = (L & 7) + ((L & 16) ? 8 : 0);  // K B-frag row offset
    const int bcg = (L >> 3) & 1;
    const int vrow_off = (L & 7) + ((L & 8) ? 8 : 0);   // V^T row offset
    const int prow = w * 16 + (L >> 2);            // softmax-owned row
    const int pxr = prow & 7;
    const int arx = arow & 7;

    for (int t = 0; t < 32; t++) {
        const int cur = t & 1;
        if (t + 1 < 32) { kvissue(1 - cur, t + 1); CPA_COMMIT(); CPA_WAIT1(); }
        else { CPA_WAIT0(); }
        __syncthreads();

        const uint32_t khb = sb + SKV0 + cur * KVBUF;
        const uint32_t klb = khb + 8192;
        const uint32_t vhb = khb + 16384;

        // ---- S = Q K^T (3-pass); ks outer so qf loads amortize over np ----
#pragma unroll
        for (int i = 0; i < 8; i++) {
            S[i][0] = 0.0f; S[i][1] = 0.0f; S[i][2] = 0.0f; S[i][3] = 0.0f;
        }
#pragma unroll
        for (int ks = 0; ks < 4; ks++) {
            uint32_t qfh[4], qfl[4];
            uint32_t qoff = arow * 128 + ((((ks * 2 + acg) ^ arx) & 7) << 4);
            ldsm4(qfh, sb + SQHI + qoff);
            ldsm4(qfl, sb + SQLO + qoff);
#pragma unroll
            for (int np = 0; np < 4; np++) {
                int brow = np * 16 + brow_off;
                uint32_t offb = brow * 128 + ((((ks * 2 + bcg) ^ (brow & 7)) & 7) << 4);
                uint32_t kbh[4], kbl[4];
                ldsm4(kbh, khb + offb);
                ldsm4(kbl, klb + offb);
                mma16816(S[2 * np],     qfh, kbh[0], kbh[1]);
                mma16816(S[2 * np + 1], qfh, kbh[2], kbh[3]);
                mma16816(S[2 * np],     qfl, kbh[0], kbh[1]);
                mma16816(S[2 * np + 1], qfl, kbh[2], kbh[3]);
                mma16816(S[2 * np],     qfh, kbl[0], kbl[1]);
                mma16816(S[2 * np + 1], qfh, kbl[2], kbl[3]);
            }
        }

        // ---- online softmax (warp-local rows) ----
        float tm0 = -INFINITY, tm1 = -INFINITY;
#pragma unroll
        for (int i = 0; i < 8; i++) {
            tm0 = fmaxf(tm0, fmaxf(S[i][0], S[i][1]));
            tm1 = fmaxf(tm1, fmaxf(S[i][2], S[i][3]));
        }
        tm0 = fmaxf(tm0, __shfl_xor_sync(0xffffffffu, tm0, 1));
        tm0 = fmaxf(tm0, __shfl_xor_sync(0xffffffffu, tm0, 2));
        tm1 = fmaxf(tm1, __shfl_xor_sync(0xffffffffu, tm1, 1));
        tm1 = fmaxf(tm1, __shfl_xor_sync(0xffffffffu, tm1, 2));
        float mn0 = fmaxf(m0, tm0), mn1 = fmaxf(m1, tm1);
        float sc0 = __expf(m0 - mn0), sc1 = __expf(m1 - mn1);
        l0 *= sc0; l1 *= sc1;
        m0 = mn0; m1 = mn1;
#pragma unroll
        for (int i = 0; i < 8; i++) {
            O[i][0] *= sc0; O[i][1] *= sc0;
            O[i][2] *= sc1; O[i][3] *= sc1;
        }
        {
            uint32_t pb0 = (uint32_t)(SPS + prow * 128 + 4 * (L & 3));
            uint32_t pb1 = pb0 + 8 * 128;
#pragma unroll
            for (int nt = 0; nt < 8; nt++) {
                float p0 = __expf(S[nt][0] - mn0);
                float p1 = __expf(S[nt][1] - mn0);
                float p2 = __expf(S[nt][2] - mn1);
                float p3 = __expf(S[nt][3] - mn1);
                l0 += p0 + p1;
                l1 += p2 + p3;
                __half2 h01 = __floats2half2_rn(p0, p1);
                __half2 h23 = __floats2half2_rn(p2, p3);
                uint32_t gsh = (uint32_t)(((nt ^ pxr) & 7) << 4);
                *(uint32_t*)(smc + pb0 + gsh) = *reinterpret_cast<uint32_t*>(&h01);
                *(uint32_t*)(smc + pb1 + gsh) = *reinterpret_cast<uint32_t*>(&h23);
            }
        }
        __syncwarp();

        // ---- O += P V (1-pass fp16) ----
#pragma unroll
        for (int ks = 0; ks < 4; ks++) {
            uint32_t pa[4];
            uint32_t poff = arow * 128 + ((((ks * 2 + acg) ^ arx) & 7) << 4);
            ldsm4(pa, sb + SPS + poff);
#pragma unroll
            for (int np = 0; np < 4; np++) {
                int vrow = ks * 16 + vrow_off;
                uint32_t voff = vrow * 128 +
                    ((((np * 2 + ((L >> 4) & 1)) ^ (vrow & 7)) & 7) << 4);
                uint32_t vb[4];
                ldsm4t(vb, vhb + voff);
                mma16816(O[2 * np],     pa, vb[0], vb[1]);
                mma16816(O[2 * np + 1], pa, vb[2], vb[3]);
            }
        }
        __syncthreads();   // buf[cur] fully consumed before next prefetch overwrites
    }

    // ---- finalize ----
    l0 += __shfl_xor_sync(0xffffffffu, l0, 1);
    l0 += __shfl_xor_sync(0xffffffffu, l0, 2);
    l1 += __shfl_xor_sync(0xffffffffu, l1, 1);
    l1 += __shfl_xor_sync(0xffffffffu, l1, 2);
    float i0 = 1.0f / l0, i1 = 1.0f / l1;
    int r0 = q0 + prow;
    float* o0 = Out + (rowbase + r0) * D_MODEL + h * HDIM + 2 * (L & 3);
    float* o1 = o0 + 8 * D_MODEL;
#pragma unroll
    for (int nt = 0; nt < 8; nt++) {
        float2 a; a.x = O[nt][0] * i0; a.y = O[nt][1] * i0;
        float2 c; c.x = O[nt][2] * i1; c.y = O[nt][3] * i1;
        *(float2*)(o0 + nt * 8) = a;
        *(float2*)(o1 + nt * 8) = c;
    }
}

// ============================================================================
extern "C" void kernel_launch(void* const* d_in, const int* in_sizes, int n_in,
                              void* d_out, int out_size) {
    (void)in_sizes; (void)n_in; (void)out_size;
    const float* x  = (const float*)d_in[0];
    const float* Wq = (const float*)d_in[1];
    const float* bq = (const float*)d_in[2];
    const float* Wk = (const float*)d_in[3];
    const float* bk = (const float*)d_in[4];
    const float* Wv = (const float*)d_in[5];
    const float* bv = (const float*)d_in[6];
    float* out = (float*)d_out;

    __half *xh, *xl, *wh, *wl, *qh, *ql, *kh, *kl, *vh;
    cudaGetSymbolAddress((void**)&xh, g_Xh);
    cudaGetSymbolAddress((void**)&xl, g_Xl);
    cudaGetSymbolAddress((void**)&wh, g_Wh);
    cudaGetSymbolAddress((void**)&wl, g_Wl);
    cudaGetSymbolAddress((void**)&qh, g_Qhi);
    cudaGetSymbolAddress((void**)&ql, g_Qlo);
    cudaGetSymbolAddress((void**)&kh, g_Khi);
    cudaGetSymbolAddress((void**)&kl, g_Klo);
    cudaGetSymbolAddress((void**)&vh, g_Vhi);

    // Unconditional (idempotent): no static guards allowed in kernel_launch.
    cudaFuncSetAttribute(qkv_hmma, cudaFuncAttributeMaxDynamicSharedMemorySize,
                         GEMM_SMEM);
    cudaFuncSetAttribute(attn_hmma, cudaFuncAttributeMaxDynamicSharedMemorySize,
                         ATTN_SMEM);

    // 1) split inputs to fp16 hi/lo
    const int xn4 = MTOT * D_MODEL / 4;       // 1048576
    const int wn4 = D_MODEL * D_MODEL / 4;    // 262144
    split_x<<<xn4 / 256, 256>>>(x, xh, xl);
    dim3 wgrid(wn4 / 256, 3);
    split_w<<<wgrid, 256>>>(Wq, Wk, Wv, wh, wl);

    // 2) HMMA QKV projection
    dim3 ggrid(24, MTOT / 128);
    qkv_hmma<<<ggrid, 256, GEMM_SMEM>>>(xh, xl, wh, wl, bq, bk, bv,
                                        qh, ql, kh, kl, vh);

    // 3) HMMA flash attention
    dim3 agrid(SEQ / 128, BATCH * NHEADS);
    attn_hmma<<<agrid, 256, ATTN_SMEM>>>(qh, ql, kh, kl, vh, out);
}